// round 1
// baseline (speedup 1.0000x reference)
#include <cuda_runtime.h>
#include <math.h>

#define NB      8
#define NODE    1024
#define TT      12
#define DIN     16
#define HID     32
#define HEADS   3
#define CD      384         // C = GAT_OUT*T = F_IN
#define NNODES  8192
#define NE      65536
#define PLEN    6

// ---------------- scratch (static device memory; no runtime allocation) ----------------
__device__ float    g_gatin [NNODES*CD];          // GRU output, [N,384]
__device__ float    g_vsrc  [CD*HEADS];           // Wgat^T @ att_src, [f][h]
__device__ float    g_vdst  [CD*HEADS];
__device__ float    g_kedge [HEADS];
__device__ float    g_Bmat  [CD*HEADS*CD];        // permuted Wgat: [c][h*384+f]
__device__ float    g_asrc  [NNODES*HEADS];
__device__ float    g_adst  [NNODES*HEADS];
__device__ unsigned g_amax  [NNODES*HEADS];       // encoded float max
__device__ float    g_denom [NNODES*HEADS];
__device__ float    g_logit [NE*HEADS];
__device__ float    g_w     [NE*HEADS];
__device__ int      g_count [NNODES];
__device__ int      g_off   [NNODES+1];
__device__ int      g_cur   [NNODES];
__device__ int      g_sorted[NE];
__device__ float    g_z     [NNODES*HEADS*CD];    // aggregated features, [N,3,384]
__device__ float    g_gatout[NNODES*CD];          // GAT output, [N,384]
__device__ unsigned g_pooled[NB*CD];              // encoded float max

// order-preserving float <-> uint for atomicMax
__device__ __forceinline__ unsigned fenc(float f){
    unsigned u = __float_as_uint(f);
    return (u & 0x80000000u) ? ~u : (u | 0x80000000u);
}
__device__ __forceinline__ float fdec(unsigned u){
    unsigned v = (u & 0x80000000u) ? (u & 0x7fffffffu) : ~u;
    return __uint_as_float(v);
}

// ---------------- init ----------------
__global__ void k_init(){
    int i = blockIdx.x*blockDim.x + threadIdx.x;
    unsigned neg = fenc(-3.0e38f);
    if (i < NNODES) g_count[i] = 0;
    if (i < NNODES*HEADS){ g_amax[i] = neg; g_denom[i] = 0.f; }
    if (i < NB*CD) g_pooled[i] = neg;
}

// ---------------- precompute attention projection vectors ----------------
__global__ void k_prep_vec(const float* __restrict__ Wgat, const float* __restrict__ att_src,
                           const float* __restrict__ att_dst, const float* __restrict__ Wedge,
                           const float* __restrict__ att_edge){
    int id = blockIdx.x*blockDim.x + threadIdx.x;
    if (id < CD*HEADS){
        int h = id / CD, f = id % CD;
        float s1 = 0.f, s2 = 0.f;
        for (int c = 0; c < CD; c++){
            float wv = Wgat[((size_t)(h*CD + c))*CD + f];
            s1 += wv * att_src[h*CD + c];
            s2 += wv * att_dst[h*CD + c];
        }
        g_vsrc[f*HEADS + h] = s1;
        g_vdst[f*HEADS + h] = s2;
    } else if (id < CD*HEADS + HEADS){
        int h = id - CD*HEADS;
        float s = 0.f;
        for (int c = 0; c < CD; c++) s += Wedge[h*CD + c] * att_edge[h*CD + c];
        g_kedge[h] = s;
    }
}

// Bmat[c][h*384+f] = Wgat[(h*384+c)][f]
__global__ void k_prep_bmat(const float* __restrict__ Wgat){
    int idx = blockIdx.x*blockDim.x + threadIdx.x;
    if (idx < CD*HEADS*CD){
        int c = idx / (HEADS*CD);
        int r = idx % (HEADS*CD);
        int h = r / CD, f = r % CD;
        g_Bmat[idx] = Wgat[((size_t)(h*CD + c))*CD + f];
    }
}

// ---------------- GRU: one warp per node ----------------
__global__ void __launch_bounds__(256) k_gru(const float* __restrict__ x,
                                             const float* __restrict__ Wih,
                                             const float* __restrict__ Whh,
                                             const float* __restrict__ bih,
                                             const float* __restrict__ bhh){
    __shared__ float sWih[96][17];   // padded: (17c+d)%32 distinct across lanes
    __shared__ float sWhh[96][33];   // padded: (33c+k)%32 distinct across lanes
    __shared__ float sbih[96];
    __shared__ float sbhh[96];
    int tid = threadIdx.x;
    for (int i = tid; i < 96*16; i += 256) sWih[i>>4][i&15] = Wih[i];
    for (int i = tid; i < 96*32; i += 256) sWhh[i>>5][i&31] = Whh[i];
    if (tid < 96){ sbih[tid] = bih[tid]; sbhh[tid] = bhh[tid]; }
    __syncthreads();

    int warp = tid >> 5, c = tid & 31;
    int n = blockIdx.x*8 + warp;
    float h = 0.f;
    const float* xrow = x + (size_t)n*TT*DIN;

    for (int t = 0; t < TT; t++){
        float xv = (c < DIN) ? xrow[t*DIN + c] : 0.f;
        float air = sbih[c], aiz = sbih[32+c], ain = sbih[64+c];
        #pragma unroll
        for (int d = 0; d < DIN; d++){
            float xd = __shfl_sync(0xffffffffu, xv, d);
            air += sWih[c][d]    * xd;
            aiz += sWih[32+c][d] * xd;
            ain += sWih[64+c][d] * xd;
        }
        float ahr = sbhh[c], ahz = sbhh[32+c], ahn = sbhh[64+c];
        #pragma unroll
        for (int k = 0; k < HID; k++){
            float hk = __shfl_sync(0xffffffffu, h, k);
            ahr += sWhh[c][k]    * hk;
            ahz += sWhh[32+c][k] * hk;
            ahn += sWhh[64+c][k] * hk;
        }
        float r  = 1.f/(1.f + __expf(-(air+ahr)));
        float z  = 1.f/(1.f + __expf(-(aiz+ahz)));
        float nn = tanhf(ain + r*ahn);
        h = (1.f - z)*nn + z*h;
        g_gatin[(size_t)n*CD + t*HID + c] = h;
    }
}

// ---------------- per-node attention logit parts: warp per node ----------------
__global__ void k_asrc(){
    int warp = threadIdx.x >> 5, lane = threadIdx.x & 31;
    int n = blockIdx.x*8 + warp;
    float s0=0,s1=0,s2=0,d0=0,d1=0,d2=0;
    const float* row = g_gatin + (size_t)n*CD;
    for (int f = lane; f < CD; f += 32){
        float g = row[f];
        s0 += g*g_vsrc[f*3+0]; s1 += g*g_vsrc[f*3+1]; s2 += g*g_vsrc[f*3+2];
        d0 += g*g_vdst[f*3+0]; d1 += g*g_vdst[f*3+1]; d2 += g*g_vdst[f*3+2];
    }
    #pragma unroll
    for (int o = 16; o; o >>= 1){
        s0 += __shfl_xor_sync(0xffffffffu, s0, o);
        s1 += __shfl_xor_sync(0xffffffffu, s1, o);
        s2 += __shfl_xor_sync(0xffffffffu, s2, o);
        d0 += __shfl_xor_sync(0xffffffffu, d0, o);
        d1 += __shfl_xor_sync(0xffffffffu, d1, o);
        d2 += __shfl_xor_sync(0xffffffffu, d2, o);
    }
    if (lane == 0){
        g_asrc[n*3+0]=s0; g_asrc[n*3+1]=s1; g_asrc[n*3+2]=s2;
        g_adst[n*3+0]=d0; g_adst[n*3+1]=d1; g_adst[n*3+2]=d2;
    }
}

// ---------------- counting sort of edges by dst ----------------
__global__ void k_count(const int* __restrict__ ei){
    int e = blockIdx.x*blockDim.x + threadIdx.x;
    if (e < NE) atomicAdd(&g_count[ei[NE + e]], 1);
}

__global__ void k_scan(){
    __shared__ int sh[1024];
    int t = threadIdx.x;
    int loc[8];
    int base = t*8;
    int s = 0;
    #pragma unroll
    for (int i = 0; i < 8; i++){ loc[i] = s; s += g_count[base+i]; }
    sh[t] = s; __syncthreads();
    for (int off = 1; off < 1024; off <<= 1){
        int v = (t >= off) ? sh[t-off] : 0;
        __syncthreads();
        sh[t] += v;
        __syncthreads();
    }
    int excl = (t == 0) ? 0 : sh[t-1];
    #pragma unroll
    for (int i = 0; i < 8; i++){ int o = excl + loc[i]; g_off[base+i] = o; g_cur[base+i] = o; }
    if (t == 1023) g_off[NNODES] = excl + s;
}

__global__ void k_scatter(const int* __restrict__ ei){
    int e = blockIdx.x*blockDim.x + threadIdx.x;
    if (e >= NE) return;
    int d = ei[NE + e];
    int pos = atomicAdd(&g_cur[d], 1);
    g_sorted[pos] = e;
}

// ---------------- edge logits + segment max ----------------
__global__ void k_edge_logit(const int* __restrict__ ei, const float* __restrict__ ea){
    int e = blockIdx.x*blockDim.x + threadIdx.x;
    if (e >= NE) return;
    int s = ei[e], d = ei[NE + e];
    float eav = ea[e];
    #pragma unroll
    for (int h = 0; h < HEADS; h++){
        float l = g_asrc[s*3+h] + g_adst[d*3+h] + eav*g_kedge[h];
        l = (l > 0.f) ? l : 0.2f*l;            // leaky_relu 0.2
        g_logit[e*3+h] = l;
        atomicMax(&g_amax[d*3+h], fenc(l));
    }
}

// ---------------- exp + segment sum ----------------
__global__ void k_edge_w(const int* __restrict__ ei){
    int e = blockIdx.x*blockDim.x + threadIdx.x;
    if (e >= NE) return;
    int d = ei[NE + e];
    #pragma unroll
    for (int h = 0; h < HEADS; h++){
        float w = __expf(g_logit[e*3+h] - fdec(g_amax[d*3+h]));
        g_w[e*3+h] = w;
        atomicAdd(&g_denom[d*3+h], w);
    }
}

// ---------------- aggregation: block per dst node (atomic-free) ----------------
__global__ void __launch_bounds__(128) k_agg(const int* __restrict__ ei){
    int n = blockIdx.x;
    int tid = threadIdx.x;    // 128: owns channels f = tid, tid+128, tid+256
    int s0 = g_off[n], s1 = g_off[n+1];
    float inv0 = (1.f/3.f)/(g_denom[n*3+0] + 1e-16f);
    float inv1 = (1.f/3.f)/(g_denom[n*3+1] + 1e-16f);
    float inv2 = (1.f/3.f)/(g_denom[n*3+2] + 1e-16f);
    float a00=0,a01=0,a02=0, a10=0,a11=0,a12=0, a20=0,a21=0,a22=0;
    for (int i = s0; i < s1; i++){
        int e   = g_sorted[i];
        int src = ei[e];
        float c0 = g_w[e*3+0]*inv0;
        float c1 = g_w[e*3+1]*inv1;
        float c2 = g_w[e*3+2]*inv2;
        const float* xr = g_gatin + (size_t)src*CD;
        float v0 = xr[tid], v1 = xr[tid+128], v2 = xr[tid+256];
        a00 += c0*v0; a01 += c0*v1; a02 += c0*v2;
        a10 += c1*v0; a11 += c1*v1; a12 += c1*v2;
        a20 += c2*v0; a21 += c2*v1; a22 += c2*v2;
    }
    float* zr = g_z + (size_t)n*(HEADS*CD);
    zr[0*CD+tid]=a00; zr[0*CD+tid+128]=a01; zr[0*CD+tid+256]=a02;
    zr[1*CD+tid]=a10; zr[1*CD+tid+128]=a11; zr[1*CD+tid+256]=a12;
    zr[2*CD+tid]=a20; zr[2*CD+tid+128]=a21; zr[2*CD+tid+256]=a22;
}

// ---------------- GEMM: gatout[8192,384] = z[8192,1152] @ Bmat^T + bias ----------------
// 128x64 tile, BK=16, 128 threads, 8x8 per thread, packed f32x2 FMA.
__global__ void __launch_bounds__(128) k_gemm(const float* __restrict__ bias){
    __shared__ float As[16][132];
    __shared__ float Bs[16][68];
    int tid = threadIdx.x;
    int m0 = blockIdx.y*128;
    int n0 = blockIdx.x*64;
    int ty = tid >> 3, tx = tid & 7;
    int lrow = tid >> 2, lcol = (tid & 3) << 2;
    unsigned long long acc[8][4];
    #pragma unroll
    for (int i = 0; i < 8; i++)
        #pragma unroll
        for (int j = 0; j < 4; j++) acc[i][j] = 0ull;
    const int K = HEADS*CD;   // 1152

    for (int k0 = 0; k0 < K; k0 += 16){
        #pragma unroll
        for (int p = 0; p < 4; p++){
            int m = lrow + p*32;
            const float4 v = *(const float4*)(g_z + (size_t)(m0+m)*K + k0 + lcol);
            As[lcol+0][m]=v.x; As[lcol+1][m]=v.y; As[lcol+2][m]=v.z; As[lcol+3][m]=v.w;
        }
        #pragma unroll
        for (int p = 0; p < 2; p++){
            int nn = lrow + p*32;
            const float4 v = *(const float4*)(g_Bmat + (size_t)(n0+nn)*K + k0 + lcol);
            Bs[lcol+0][nn]=v.x; Bs[lcol+1][nn]=v.y; Bs[lcol+2][nn]=v.z; Bs[lcol+3][nn]=v.w;
        }
        __syncthreads();
        #pragma unroll
        for (int kk = 0; kk < 16; kk++){
            float a[8];
            *(float4*)&a[0] = *(const float4*)&As[kk][ty*8];
            *(float4*)&a[4] = *(const float4*)&As[kk][ty*8+4];
            unsigned long long bp[4];
            #pragma unroll
            for (int j = 0; j < 4; j++)
                bp[j] = *(const unsigned long long*)&Bs[kk][tx*8 + 2*j];
            #pragma unroll
            for (int i = 0; i < 8; i++){
                unsigned long long ap;
                asm("mov.b64 %0, {%1, %2};" : "=l"(ap) : "f"(a[i]), "f"(a[i]));
                #pragma unroll
                for (int j = 0; j < 4; j++)
                    asm("fma.rn.f32x2 %0, %1, %2, %3;"
                        : "=l"(acc[i][j]) : "l"(ap), "l"(bp[j]), "l"(acc[i][j]));
            }
        }
        __syncthreads();
    }
    float bloc[8];
    #pragma unroll
    for (int j = 0; j < 8; j++) bloc[j] = bias[n0 + tx*8 + j];
    #pragma unroll
    for (int i = 0; i < 8; i++){
        int m = m0 + ty*8 + i;
        float o[8];
        #pragma unroll
        for (int j = 0; j < 4; j++){
            float lo, hi;
            asm("mov.b64 {%0, %1}, %2;" : "=f"(lo), "=f"(hi) : "l"(acc[i][j]));
            o[2*j]   = lo + bloc[2*j];
            o[2*j+1] = hi + bloc[2*j+1];
        }
        float4* dst = (float4*)(g_gatout + (size_t)m*CD + n0 + tx*8);
        dst[0] = make_float4(o[0],o[1],o[2],o[3]);
        dst[1] = make_float4(o[4],o[5],o[6],o[7]);
    }
}

// ---------------- predictor: warp per node ----------------
__global__ void k_pred(const float* __restrict__ Wp1, const float* __restrict__ bp1,
                       const float* __restrict__ Wp3, const float* __restrict__ bp3,
                       float* __restrict__ out){
    int warp = threadIdx.x >> 5, lane = threadIdx.x & 31;
    int n = blockIdx.x*8 + warp;
    const float* row = g_gatout + (size_t)n*CD;
    float w1 = Wp1[lane];
    float b1 = bp1[0];
    float p[TT];
    #pragma unroll
    for (int t = 0; t < TT; t++){
        float s = row[t*HID + lane]*w1;
        #pragma unroll
        for (int o = 16; o; o >>= 1) s += __shfl_xor_sync(0xffffffffu, s, o);
        s += b1;
        p[t] = (s > 0.f) ? s : 0.f;
    }
    if (lane < PLEN){
        float q = bp3[lane];
        #pragma unroll
        for (int t = 0; t < TT; t++) q += p[t]*Wp3[lane*TT + t];
        out[(size_t)n*PLEN + lane] = (q > 0.f) ? q : 0.f;
    }
}

// ---------------- batch max-pool ----------------
__global__ void k_pool(const int* __restrict__ bv){
    int g0 = blockIdx.x*128;
    int c  = threadIdx.x;       // 384
    int b  = bv[g0];            // 128-node range never crosses a batch boundary (1024 | 128)
    float m = -3.0e38f;
    for (int i = 0; i < 128; i++){
        float v = g_gatout[(size_t)(g0+i)*CD + c];
        m = fmaxf(m, v);
    }
    atomicMax(&g_pooled[b*CD + c], fenc(m));
}

// ---------------- classifier + softmax ----------------
__global__ void k_cls(const float* __restrict__ Wc1, const float* __restrict__ bc1,
                      const float* __restrict__ Wc2, const float* __restrict__ bc2,
                      float* __restrict__ out, int out_size){
    __shared__ float l1[NB][32];
    __shared__ float l2[NB][2];
    int tid = threadIdx.x;      // 256 = 8 batches x 32 outputs
    int b = tid >> 5, i = tid & 31;
    float a = bc1[i];
    for (int c = 0; c < CD; c++) a += fdec(g_pooled[b*CD + c]) * Wc1[i*CD + c];
    l1[b][i] = a;
    __syncthreads();
    if (tid < NB*2){
        int bb = tid >> 1, j = tid & 1;
        float v = bc2[j];
        for (int k = 0; k < 32; k++) v += l1[bb][k]*Wc2[j*32 + k];
        l2[bb][j] = v;
    }
    __syncthreads();
    if (tid < NB*2){
        int bb = tid >> 1, j = tid & 1;
        float m = fmaxf(l2[bb][0], l2[bb][1]);
        float e0 = __expf(l2[bb][0] - m), e1 = __expf(l2[bb][1] - m);
        out[out_size - NB*2 + bb*2 + j] = ((j == 0) ? e0 : e1) / (e0 + e1);
    }
}

// ---------------- launch ----------------
extern "C" void kernel_launch(void* const* d_in, const int* in_sizes, int n_in,
                              void* d_out, int out_size){
    const float* x   = (const float*)d_in[0];
    const int*   ei  = (const int*)  d_in[1];
    const float* ea  = (const float*)d_in[2];
    const int*   bv  = (const int*)  d_in[3];
    // 'alpha' is a python scalar; detect whether it appears as a 1-element input
    int wb = (n_in >= 23 && in_sizes[4] == 1) ? 5 : 4;
    const float* Wih      = (const float*)d_in[wb+0];
    const float* Whh      = (const float*)d_in[wb+1];
    const float* bih      = (const float*)d_in[wb+2];
    const float* bhh      = (const float*)d_in[wb+3];
    const float* Wgat     = (const float*)d_in[wb+4];
    const float* att_src  = (const float*)d_in[wb+5];
    const float* att_dst  = (const float*)d_in[wb+6];
    const float* Wedge    = (const float*)d_in[wb+7];
    const float* att_edge = (const float*)d_in[wb+8];
    const float* gat_bias = (const float*)d_in[wb+9];
    const float* Wp1      = (const float*)d_in[wb+10];
    const float* bp1      = (const float*)d_in[wb+11];
    const float* Wp3      = (const float*)d_in[wb+12];
    const float* bp3      = (const float*)d_in[wb+13];
    const float* Wc1      = (const float*)d_in[wb+14];
    const float* bc1      = (const float*)d_in[wb+15];
    const float* Wc2      = (const float*)d_in[wb+16];
    const float* bc2      = (const float*)d_in[wb+17];
    float* out = (float*)d_out;

    k_init      <<<96, 256>>>();
    k_prep_vec  <<<5, 256>>>(Wgat, att_src, att_dst, Wedge, att_edge);
    k_prep_bmat <<<1728, 256>>>(Wgat);
    k_gru       <<<1024, 256>>>(x, Wih, Whh, bih, bhh);
    k_asrc      <<<1024, 256>>>();
    k_count     <<<NE/256, 256>>>(ei);
    k_scan      <<<1, 1024>>>();
    k_scatter   <<<NE/256, 256>>>(ei);
    k_edge_logit<<<NE/256, 256>>>(ei, ea);
    k_edge_w    <<<NE/256, 256>>>(ei);
    k_agg       <<<NNODES, 128>>>(ei);
    k_gemm      <<<dim3(CD/64, NNODES/128), 128>>>(gat_bias);
    k_pred      <<<1024, 256>>>(Wp1, bp1, Wp3, bp3, out);
    k_pool      <<<64, 384>>>(bv);
    k_cls       <<<1, 256>>>(Wc1, bc1, Wc2, bc2, out, out_size);
}

// round 3
// speedup vs baseline: 1.2951x; 1.2951x over previous
#include <cuda_runtime.h>
#include <cuda_bf16.h>
#include <math.h>

#define NB      8
#define NODE    1024
#define TT      12
#define DIN     16
#define HID     32
#define HEADS   3
#define CD      384
#define NNODES  8192
#define NE      65536
#define PLEN    6
#define KDIM    1152        // HEADS*CD

// ---------------- scratch (static device memory) ----------------
__device__ float          g_gatin [NNODES*CD];
__device__ float          g_gi    [NNODES*TT*96];   // precomputed input gates (+biases)
__device__ float          g_WhhT  [3*32*32];        // [gate][k][c]
__device__ float          g_vsrc  [CD*HEADS];
__device__ float          g_vdst  [CD*HEADS];
__device__ float          g_kedge [HEADS];
__device__ __nv_bfloat16  g_Bhi16 [CD*KDIM];        // B[n][k] row-major bf16 hi
__device__ __nv_bfloat16  g_Blo16 [CD*KDIM];        // residual lo
__device__ float          g_asrc  [NNODES*HEADS];
__device__ float          g_adst  [NNODES*HEADS];
__device__ unsigned       g_amax  [NNODES*HEADS];
__device__ float          g_denom [NNODES*HEADS];
__device__ float          g_logit [NE*HEADS];
__device__ float          g_w     [NE*HEADS];
__device__ int            g_count [NNODES];
__device__ int            g_off   [NNODES+1];
__device__ int            g_cur   [NNODES];
__device__ int            g_sorted[NE];
__device__ __nv_bfloat16  g_Zhi   [NNODES*KDIM];
__device__ __nv_bfloat16  g_Zlo   [NNODES*KDIM];
__device__ float          g_gatout[NNODES*CD];
__device__ unsigned       g_pooled[NB*CD];

// order-preserving float <-> uint for atomicMax
__device__ __forceinline__ unsigned fenc(float f){
    unsigned u = __float_as_uint(f);
    return (u & 0x80000000u) ? ~u : (u | 0x80000000u);
}
__device__ __forceinline__ float fdec(unsigned u){
    unsigned v = (u & 0x80000000u) ? (u & 0x7fffffffu) : ~u;
    return __uint_as_float(v);
}

__device__ __forceinline__ unsigned smem_u32(const void* p){
    unsigned a;
    asm("{ .reg .u64 t; cvta.to.shared.u64 t, %1; cvt.u32.u64 %0, t; }" : "=r"(a) : "l"(p));
    return a;
}

// ---------------- mma.sync helpers (sm_80-era, valid on base sm_103) ----------------
#define LDSM4(r, a)                                                                 \
    asm volatile("ldmatrix.sync.aligned.m8n8.x4.shared.b16 {%0,%1,%2,%3}, [%4];"    \
        : "=r"((r)[0]), "=r"((r)[1]), "=r"((r)[2]), "=r"((r)[3]) : "r"(a))

#define MMA16816(d, a, b)                                                           \
    asm volatile("mma.sync.aligned.m16n8k16.row.col.f32.bf16.bf16.f32 "             \
        "{%0,%1,%2,%3}, {%4,%5,%6,%7}, {%8,%9}, {%0,%1,%2,%3};"                     \
        : "+f"((d)[0]), "+f"((d)[1]), "+f"((d)[2]), "+f"((d)[3])                    \
        : "r"((a)[0]), "r"((a)[1]), "r"((a)[2]), "r"((a)[3]),                       \
          "r"((b)[0]), "r"((b)[1]))

// ---------------- init ----------------
__global__ void k_init(){
    int i = blockIdx.x*blockDim.x + threadIdx.x;
    unsigned neg = fenc(-3.0e38f);
    if (i < NNODES) g_count[i] = 0;
    if (i < NNODES*HEADS){ g_amax[i] = neg; g_denom[i] = 0.f; }
    if (i < NB*CD) g_pooled[i] = neg;
}

// ---------------- attention projection vectors ----------------
__global__ void k_prep_vec(const float* __restrict__ Wgat, const float* __restrict__ att_src,
                           const float* __restrict__ att_dst, const float* __restrict__ Wedge,
                           const float* __restrict__ att_edge){
    int id = blockIdx.x*blockDim.x + threadIdx.x;
    if (id < CD*HEADS){
        int h = id / CD, f = id % CD;
        float s1 = 0.f, s2 = 0.f;
        for (int c = 0; c < CD; c++){
            float wv = Wgat[((size_t)(h*CD + c))*CD + f];
            s1 += wv * att_src[h*CD + c];
            s2 += wv * att_dst[h*CD + c];
        }
        g_vsrc[f*HEADS + h] = s1;
        g_vdst[f*HEADS + h] = s2;
    } else if (id < CD*HEADS + HEADS){
        int h = id - CD*HEADS;
        float s = 0.f;
        for (int c = 0; c < CD; c++) s += Wedge[h*CD + c] * att_edge[h*CD + c];
        g_kedge[h] = s;
    }
}

// B[c][k] = Wgat[(h*384+c)*384+f], k = h*384+f, split into bf16 hi + lo
__global__ void k_prep_b16(const float* __restrict__ Wgat){
    int idx = blockIdx.x*blockDim.x + threadIdx.x;
    if (idx >= CD*KDIM) return;
    int c = idx / KDIM, k = idx % KDIM;
    int h = k / CD, f = k % CD;
    float wv = Wgat[((size_t)(h*CD + c))*CD + f];
    __nv_bfloat16 hi = __float2bfloat16(wv);
    g_Bhi16[idx] = hi;
    g_Blo16[idx] = __float2bfloat16(wv - __bfloat162float(hi));
}

// transposed recurrent weights: g_WhhT[(gate*32+k)*32+c] = Whh[gate*32+c][k]
__global__ void k_prep_whhT(const float* __restrict__ Whh){
    int idx = blockIdx.x*blockDim.x + threadIdx.x;
    if (idx < 3072){
        int gk = idx >> 5, c = idx & 31;
        int gate = gk >> 5, k = gk & 31;
        g_WhhT[idx] = Whh[(gate*32 + c)*32 + k];
    }
}

// ---------------- input-gate precompute: g_gi[nt][96] = x@Wih^T + bih (+bhh for r,z) ----
__global__ void __launch_bounds__(256) k_prep_gi(const float* __restrict__ x,
                                                 const float* __restrict__ Wih,
                                                 const float* __restrict__ bih,
                                                 const float* __restrict__ bhh){
    __shared__ float sW[96][17];
    __shared__ float sb[96];
    int tid = threadIdx.x;
    for (int i = tid; i < 96*16; i += 256) sW[i>>4][i&15] = Wih[i];
    if (tid < 96) sb[tid] = bih[tid] + ((tid < 64) ? bhh[tid] : 0.f);
    __syncthreads();
    int lane = tid & 31, w = tid >> 5;
    int nt = blockIdx.x*8 + w;
    float xv = (lane < 16) ? x[(size_t)nt*DIN + lane] : 0.f;
    float a0 = sb[lane], a1 = sb[32+lane], a2 = sb[64+lane];
    #pragma unroll
    for (int d = 0; d < 16; d++){
        float xd = __shfl_sync(0xffffffffu, xv, d);
        a0 += sW[lane][d]*xd;
        a1 += sW[32+lane][d]*xd;
        a2 += sW[64+lane][d]*xd;
    }
    float* o = g_gi + (size_t)nt*96;
    o[lane] = a0; o[32+lane] = a1; o[64+lane] = a2;
}

// ---------------- GRU: register-resident Whh, warp per node (8 nodes/warp) -------------
// Also fuses the attention-source/dst projections (asrc/adst).
__global__ void __launch_bounds__(256) k_gru2(const float* __restrict__ bhh){
    int tid = threadIdx.x, lane = tid & 31, w = tid >> 5;
    int wg = blockIdx.x*8 + w;           // 0..1023
    float wr[32], wz[32], wn[32];
    #pragma unroll
    for (int k = 0; k < 32; k++){
        wr[k] = g_WhhT[(0*32 + k)*32 + lane];
        wz[k] = g_WhhT[(32   + k)*32 + lane];
        wn[k] = g_WhhT[(64   + k)*32 + lane];
    }
    float bn = bhh[64 + lane];

    for (int ni = 0; ni < 8; ni++){
        int n = wg*8 + ni;
        float h = 0.f;
        float s0=0,s1=0,s2=0,d0=0,d1=0,d2=0;
        const float* gi = g_gi + (size_t)n*TT*96;
        float* outp = g_gatin + (size_t)n*CD;
        for (int t = 0; t < TT; t++){
            float gr = gi[t*96 + lane], gz = gi[t*96 + 32 + lane], gn = gi[t*96 + 64 + lane];
            float ar = 0.f, az = 0.f, an = 0.f;
            #pragma unroll
            for (int k = 0; k < 32; k++){
                float hk = __shfl_sync(0xffffffffu, h, k);
                ar += wr[k]*hk; az += wz[k]*hk; an += wn[k]*hk;
            }
            float r  = 1.f/(1.f + __expf(-(gr + ar)));
            float z  = 1.f/(1.f + __expf(-(gz + az)));
            float nn = tanhf(gn + r*(an + bn));
            h = (1.f - z)*nn + z*h;
            outp[t*32 + lane] = h;
            int f = t*32 + lane;
            s0 += h*g_vsrc[f*3+0]; s1 += h*g_vsrc[f*3+1]; s2 += h*g_vsrc[f*3+2];
            d0 += h*g_vdst[f*3+0]; d1 += h*g_vdst[f*3+1]; d2 += h*g_vdst[f*3+2];
        }
        #pragma unroll
        for (int o = 16; o; o >>= 1){
            s0 += __shfl_xor_sync(0xffffffffu, s0, o);
            s1 += __shfl_xor_sync(0xffffffffu, s1, o);
            s2 += __shfl_xor_sync(0xffffffffu, s2, o);
            d0 += __shfl_xor_sync(0xffffffffu, d0, o);
            d1 += __shfl_xor_sync(0xffffffffu, d1, o);
            d2 += __shfl_xor_sync(0xffffffffu, d2, o);
        }
        if (lane == 0){
            g_asrc[n*3+0]=s0; g_asrc[n*3+1]=s1; g_asrc[n*3+2]=s2;
            g_adst[n*3+0]=d0; g_adst[n*3+1]=d1; g_adst[n*3+2]=d2;
        }
    }
}

// ---------------- edge logits + segment max + dst count (fused) ----------------
__global__ void k_elc(const int* __restrict__ ei, const float* __restrict__ ea){
    int e = blockIdx.x*blockDim.x + threadIdx.x;
    if (e >= NE) return;
    int s = ei[e], d = ei[NE + e];
    atomicAdd(&g_count[d], 1);
    float eav = ea[e];
    #pragma unroll
    for (int h = 0; h < HEADS; h++){
        float l = g_asrc[s*3+h] + g_adst[d*3+h] + eav*g_kedge[h];
        l = (l > 0.f) ? l : 0.2f*l;
        g_logit[e*3+h] = l;
        atomicMax(&g_amax[d*3+h], fenc(l));
    }
}

__global__ void k_scan(){
    __shared__ int sh[1024];
    int t = threadIdx.x;
    int loc[8];
    int base = t*8;
    int s = 0;
    #pragma unroll
    for (int i = 0; i < 8; i++){ loc[i] = s; s += g_count[base+i]; }
    sh[t] = s; __syncthreads();
    for (int off = 1; off < 1024; off <<= 1){
        int v = (t >= off) ? sh[t-off] : 0;
        __syncthreads();
        sh[t] += v;
        __syncthreads();
    }
    int excl = (t == 0) ? 0 : sh[t-1];
    #pragma unroll
    for (int i = 0; i < 8; i++){ int o = excl + loc[i]; g_off[base+i] = o; g_cur[base+i] = o; }
    if (t == 1023) g_off[NNODES] = excl + s;
}

// ---------------- scatter + exp + segment sum (fused) ----------------
__global__ void k_scw(const int* __restrict__ ei){
    int e = blockIdx.x*blockDim.x + threadIdx.x;
    if (e >= NE) return;
    int d = ei[NE + e];
    int pos = atomicAdd(&g_cur[d], 1);
    g_sorted[pos] = e;
    #pragma unroll
    for (int h = 0; h < HEADS; h++){
        float w = __expf(g_logit[e*3+h] - fdec(g_amax[d*3+h]));
        g_w[e*3+h] = w;
        atomicAdd(&g_denom[d*3+h], w);
    }
}

// ---------------- aggregation: block per dst node -> bf16 hi/lo split ----------------
__global__ void __launch_bounds__(128) k_agg(const int* __restrict__ ei){
    int n = blockIdx.x;
    int tid = threadIdx.x;
    int s0 = g_off[n], s1 = g_off[n+1];
    float inv0 = (1.f/3.f)/(g_denom[n*3+0] + 1e-16f);
    float inv1 = (1.f/3.f)/(g_denom[n*3+1] + 1e-16f);
    float inv2 = (1.f/3.f)/(g_denom[n*3+2] + 1e-16f);
    float a[3][3] = {};
    for (int i = s0; i < s1; i++){
        int e   = g_sorted[i];
        int src = ei[e];
        float c0 = g_w[e*3+0]*inv0;
        float c1 = g_w[e*3+1]*inv1;
        float c2 = g_w[e*3+2]*inv2;
        const float* xr = g_gatin + (size_t)src*CD;
        float v0 = xr[tid], v1 = xr[tid+128], v2 = xr[tid+256];
        a[0][0] += c0*v0; a[0][1] += c0*v1; a[0][2] += c0*v2;
        a[1][0] += c1*v0; a[1][1] += c1*v1; a[1][2] += c1*v2;
        a[2][0] += c2*v0; a[2][1] += c2*v1; a[2][2] += c2*v2;
    }
    #pragma unroll
    for (int hh = 0; hh < 3; hh++)
        #pragma unroll
        for (int j = 0; j < 3; j++){
            float v = a[hh][j];
            __nv_bfloat16 hi = __float2bfloat16(v);
            __nv_bfloat16 lo = __float2bfloat16(v - __bfloat162float(hi));
            size_t o = (size_t)n*KDIM + hh*CD + tid + 128*j;
            g_Zhi[o] = hi;
            g_Zlo[o] = lo;
        }
}

// ---------------- GEMM via mma.sync bf16 3-product split --------------------------------
// out[8192,384] = (Zhi+Zlo)[8192,1152] @ (Bhi+Blo)[384,1152]^T + bias
// CTA tile 128x192 (12 warps, warp tile 32x64), grid (2,64) = 128 CTAs (one wave).
// K-chunks of 64, cp.async double-buffered, padded smem rows (72 halves).
#define ROWP    72
#define A_ARR   18432u                // 128*72*2
#define B_ARR   27648u                // 192*72*2
#define OFF_AHI 0u
#define OFF_ALO 18432u
#define OFF_BHI 36864u
#define OFF_BLO 64512u
#define BUF_SZ  92160u
#define GSM_TOT (2u*BUF_SZ)           // 180 KB

__device__ __forceinline__ void gfill(unsigned sb, int tid, int buf, int kc, int m0, int n0){
    unsigned base = sb + (unsigned)buf*BUF_SZ;
    for (int u = tid; u < 5120; u += 384){
        const __nv_bfloat16* src;
        unsigned off;
        if (u < 2048){
            int arr = u >> 10, rs = u & 1023, r = rs >> 3, s = rs & 7;
            src = (arr ? g_Zlo : g_Zhi) + (size_t)(m0 + r)*KDIM + kc*64 + s*8;
            off = (unsigned)arr*A_ARR + (unsigned)(r*ROWP + s*8)*2u;
        } else {
            int v = u - 2048;
            int arr = v / 1536, rs = v % 1536, r = rs >> 3, s = rs & 7;
            src = (arr ? g_Blo16 : g_Bhi16) + (size_t)(n0 + r)*KDIM + kc*64 + s*8;
            off = OFF_BHI + (unsigned)arr*B_ARR + (unsigned)(r*ROWP + s*8)*2u;
        }
        asm volatile("cp.async.ca.shared.global [%0], [%1], 16;"
                     :: "r"(base + off), "l"(src) : "memory");
    }
    asm volatile("cp.async.commit_group;" ::: "memory");
}

__global__ void __launch_bounds__(384, 1) k_gemm_mma(const float* __restrict__ bias){
    extern __shared__ char sm[];
    unsigned sb = smem_u32(sm);
    int tid = threadIdx.x, lane = tid & 31, w = tid >> 5;
    int m0 = blockIdx.y*128, n0 = blockIdx.x*192;
    int wm = (w & 3)*32, wn = (w >> 2)*64;

    float acc[2][8][4];
    #pragma unroll
    for (int i = 0; i < 2; i++)
        #pragma unroll
        for (int j = 0; j < 8; j++)
            #pragma unroll
            for (int q = 0; q < 4; q++) acc[i][j][q] = 0.f;

    gfill(sb, tid, 0, 0, m0, n0);
    for (int kc = 0; kc < 18; kc++){
        if (kc + 1 < 18){
            gfill(sb, tid, (kc+1)&1, kc+1, m0, n0);
            asm volatile("cp.async.wait_group 1;" ::: "memory");
        } else {
            asm volatile("cp.async.wait_group 0;" ::: "memory");
        }
        __syncthreads();
        unsigned base = sb + (unsigned)(kc&1)*BUF_SZ;
        #pragma unroll
        for (int ks = 0; ks < 4; ks++){
            int kk = ks*16;
            unsigned ahi[2][4], alo[2][4];
            #pragma unroll
            for (int mi = 0; mi < 2; mi++){
                int row = wm + mi*16 + (lane & 15);
                int col = kk + 8*(lane >> 4);
                unsigned off = (unsigned)(row*ROWP + col)*2u;
                LDSM4(ahi[mi], base + OFF_AHI + off);
                LDSM4(alo[mi], base + OFF_ALO + off);
            }
            unsigned bhi[4][4], blo[4][4];
            #pragma unroll
            for (int p = 0; p < 4; p++){
                int row = wn + p*16 + (lane & 7) + 8*(lane >> 4);
                int col = kk + 8*((lane >> 3) & 1);
                unsigned off = (unsigned)(row*ROWP + col)*2u;
                LDSM4(bhi[p], base + OFF_BHI + off);
                LDSM4(blo[p], base + OFF_BLO + off);
            }
            #pragma unroll
            for (int mi = 0; mi < 2; mi++)
                #pragma unroll
                for (int nj = 0; nj < 8; nj++){
                    unsigned* bh = &bhi[nj>>1][(nj&1)*2];
                    unsigned* bl = &blo[nj>>1][(nj&1)*2];
                    MMA16816(acc[mi][nj], ahi[mi], bh);
                    MMA16816(acc[mi][nj], ahi[mi], bl);
                    MMA16816(acc[mi][nj], alo[mi], bh);
                }
        }
        __syncthreads();
    }

    int r0 = lane >> 2, c0 = 2*(lane & 3);
    #pragma unroll
    for (int mi = 0; mi < 2; mi++)
        #pragma unroll
        for (int nj = 0; nj < 8; nj++){
            int row = m0 + wm + mi*16 + r0;
            int col = n0 + wn + nj*8 + c0;
            float b0 = bias[col], b1 = bias[col+1];
            *(float2*)&g_gatout[(size_t)row*CD + col] =
                make_float2(acc[mi][nj][0] + b0, acc[mi][nj][1] + b1);
            *(float2*)&g_gatout[(size_t)(row+8)*CD + col] =
                make_float2(acc[mi][nj][2] + b0, acc[mi][nj][3] + b1);
        }
}

// ---------------- predictor: warp per node ----------------
__global__ void k_pred(const float* __restrict__ Wp1, const float* __restrict__ bp1,
                       const float* __restrict__ Wp3, const float* __restrict__ bp3,
                       float* __restrict__ out){
    int warp = threadIdx.x >> 5, lane = threadIdx.x & 31;
    int n = blockIdx.x*8 + warp;
    const float* row = g_gatout + (size_t)n*CD;
    float w1 = Wp1[lane];
    float b1 = bp1[0];
    float p[TT];
    #pragma unroll
    for (int t = 0; t < TT; t++){
        float s = row[t*HID + lane]*w1;
        #pragma unroll
        for (int o = 16; o; o >>= 1) s += __shfl_xor_sync(0xffffffffu, s, o);
        s += b1;
        p[t] = (s > 0.f) ? s : 0.f;
    }
    if (lane < PLEN){
        float q = bp3[lane];
        #pragma unroll
        for (int t = 0; t < TT; t++) q += p[t]*Wp3[lane*TT + t];
        out[(size_t)n*PLEN + lane] = (q > 0.f) ? q : 0.f;
    }
}

// ---------------- batch max-pool ----------------
__global__ void k_pool(const int* __restrict__ bv){
    int g0 = blockIdx.x*128;
    int c  = threadIdx.x;
    int b  = bv[g0];
    float m = -3.0e38f;
    for (int i = 0; i < 128; i++){
        float v = g_gatout[(size_t)(g0+i)*CD + c];
        m = fmaxf(m, v);
    }
    atomicMax(&g_pooled[b*CD + c], fenc(m));
}

// ---------------- classifier + softmax ----------------
__global__ void k_cls(const float* __restrict__ Wc1, const float* __restrict__ bc1,
                      const float* __restrict__ Wc2, const float* __restrict__ bc2,
                      float* __restrict__ out, int out_size){
    __shared__ float l1[NB][32];
    __shared__ float l2[NB][2];
    int tid = threadIdx.x;
    int b = tid >> 5, i = tid & 31;
    float a = bc1[i];
    for (int c = 0; c < CD; c++) a += fdec(g_pooled[b*CD + c]) * Wc1[i*CD + c];
    l1[b][i] = a;
    __syncthreads();
    if (tid < NB*2){
        int bb = tid >> 1, j = tid & 1;
        float v = bc2[j];
        for (int k = 0; k < 32; k++) v += l1[bb][k]*Wc2[j*32 + k];
        l2[bb][j] = v;
    }
    __syncthreads();
    if (tid < NB*2){
        int bb = tid >> 1, j = tid & 1;
        float m = fmaxf(l2[bb][0], l2[bb][1]);
        float e0 = __expf(l2[bb][0] - m), e1 = __expf(l2[bb][1] - m);
        out[out_size - NB*2 + bb*2 + j] = ((j == 0) ? e0 : e1) / (e0 + e1);
    }
}

// ---------------- launch ----------------
extern "C" void kernel_launch(void* const* d_in, const int* in_sizes, int n_in,
                              void* d_out, int out_size){
    const float* x   = (const float*)d_in[0];
    const int*   ei  = (const int*)  d_in[1];
    const float* ea  = (const float*)d_in[2];
    const int*   bv  = (const int*)  d_in[3];
    int wb = (n_in >= 23 && in_sizes[4] == 1) ? 5 : 4;
    const float* Wih      = (const float*)d_in[wb+0];
    const float* Whh      = (const float*)d_in[wb+1];
    const float* bih      = (const float*)d_in[wb+2];
    const float* bhh      = (const float*)d_in[wb+3];
    const float* Wgat     = (const float*)d_in[wb+4];
    const float* att_src  = (const float*)d_in[wb+5];
    const float* att_dst  = (const float*)d_in[wb+6];
    const float* Wedge    = (const float*)d_in[wb+7];
    const float* att_edge = (const float*)d_in[wb+8];
    const float* gat_bias = (const float*)d_in[wb+9];
    const float* Wp1      = (const float*)d_in[wb+10];
    const float* bp1      = (const float*)d_in[wb+11];
    const float* Wp3      = (const float*)d_in[wb+12];
    const float* bp3      = (const float*)d_in[wb+13];
    const float* Wc1      = (const float*)d_in[wb+14];
    const float* bc1      = (const float*)d_in[wb+15];
    const float* Wc2      = (const float*)d_in[wb+16];
    const float* bc2      = (const float*)d_in[wb+17];
    float* out = (float*)d_out;

    cudaFuncSetAttribute(k_gemm_mma, cudaFuncAttributeMaxDynamicSharedMemorySize, GSM_TOT);

    k_init      <<<96, 256>>>();
    k_prep_vec  <<<5, 256>>>(Wgat, att_src, att_dst, Wedge, att_edge);
    k_prep_b16  <<<(CD*KDIM + 255)/256, 256>>>(Wgat);
    k_prep_whhT <<<12, 256>>>(Whh);
    k_prep_gi   <<<NNODES*TT/8, 256>>>(x, Wih, bih, bhh);
    k_gru2      <<<128, 256>>>(bhh);
    k_elc       <<<NE/256, 256>>>(ei, ea);
    k_scan      <<<1, 1024>>>();
    k_scw       <<<NE/256, 256>>>(ei);
    k_agg       <<<NNODES, 128>>>(ei);
    k_gemm_mma  <<<dim3(2, 64), 384, GSM_TOT>>>(gat_bias);
    k_pred      <<<1024, 256>>>(Wp1, bp1, Wp3, bp3, out);
    k_pool      <<<64, 384>>>(bv);
    k_cls       <<<1, 256>>>(Wc1, bc1, Wc2, bc2, out, out_size);
}

// round 4
// speedup vs baseline: 1.7292x; 1.3352x over previous
#include <cuda_runtime.h>
#include <cuda_fp16.h>
#include <math.h>

#define NB      8
#define NODE    1024
#define TT      12
#define DIN     16
#define HID     32
#define HEADS   3
#define CD      384
#define NNODES  8192
#define NE      65536
#define PLEN    6
#define KDIM    1152        // HEADS*CD

// ---------------- scratch (static device memory) ----------------
__device__ float    g_gatin [NNODES*CD];
__device__ float    g_vsrc  [CD*HEADS];
__device__ float    g_vdst  [CD*HEADS];
__device__ float    g_kedge [HEADS];
__device__ __half   g_B16   [CD*KDIM];      // B[n][k] row-major fp16
__device__ float    g_asrc  [NNODES*HEADS];
__device__ float    g_adst  [NNODES*HEADS];
__device__ unsigned g_amax  [NNODES*HEADS];
__device__ float    g_denom [NNODES*HEADS];
__device__ float    g_logit [NE*HEADS];
__device__ float    g_w     [NE*HEADS];
__device__ int      g_count [NNODES];
__device__ int      g_off   [NNODES+1];
__device__ int      g_cur   [NNODES];
__device__ int      g_sorted[NE];
__device__ __half   g_Zhi   [NNODES*KDIM];
__device__ __half   g_Zlo   [NNODES*KDIM];
__device__ float    g_gatout[NNODES*CD];
__device__ unsigned g_pooled[NB*CD];

// order-preserving float <-> uint for atomicMax
__device__ __forceinline__ unsigned fenc(float f){
    unsigned u = __float_as_uint(f);
    return (u & 0x80000000u) ? ~u : (u | 0x80000000u);
}
__device__ __forceinline__ float fdec(unsigned u){
    unsigned v = (u & 0x80000000u) ? (u & 0x7fffffffu) : ~u;
    return __uint_as_float(v);
}

__device__ __forceinline__ unsigned smem_u32(const void* p){
    unsigned a;
    asm("{ .reg .u64 t; cvta.to.shared.u64 t, %1; cvt.u32.u64 %0, t; }" : "=r"(a) : "l"(p));
    return a;
}

// ---------------- mma.sync helpers (sm_80-era, valid on base sm_103) ----------------
#define LDSM4(r, a)                                                                 \
    asm volatile("ldmatrix.sync.aligned.m8n8.x4.shared.b16 {%0,%1,%2,%3}, [%4];"    \
        : "=r"((r)[0]), "=r"((r)[1]), "=r"((r)[2]), "=r"((r)[3]) : "r"(a))

#define MMAF16(d, a, b)                                                             \
    asm volatile("mma.sync.aligned.m16n8k16.row.col.f32.f16.f16.f32 "               \
        "{%0,%1,%2,%3}, {%4,%5,%6,%7}, {%8,%9}, {%0,%1,%2,%3};"                     \
        : "+f"((d)[0]), "+f"((d)[1]), "+f"((d)[2]), "+f"((d)[3])                    \
        : "r"((a)[0]), "r"((a)[1]), "r"((a)[2]), "r"((a)[3]),                       \
          "r"((b)[0]), "r"((b)[1]))

// ---------------- init: zero/neg-fill scratch + kedge ----------------
__global__ void k_init(const float* __restrict__ Wedge, const float* __restrict__ att_edge){
    int i = blockIdx.x*blockDim.x + threadIdx.x;
    unsigned neg = fenc(-3.0e38f);
    if (i < NNODES) g_count[i] = 0;
    if (i < NNODES*HEADS){ g_amax[i] = neg; g_denom[i] = 0.f; }
    if (i < NB*CD) g_pooled[i] = neg;
    if (i < CD*HEADS){ g_vsrc[i] = 0.f; g_vdst[i] = 0.f; }
    if (i < 96){                       // 3 warps: kedge[h] via warp reduce
        int h = i >> 5, lane = i & 31;
        float s = 0.f;
        for (int c = lane; c < CD; c += 32) s += Wedge[h*CD + c]*att_edge[h*CD + c];
        #pragma unroll
        for (int o = 16; o; o >>= 1) s += __shfl_xor_sync(0xffffffffu, s, o);
        if (lane == 0) g_kedge[h] = s;
    }
}

// ---------------- B fp16 + attention projection vectors (fused) ----------------
// B[c][k] = Wgat[(h*384+c)*384+f], k = h*384+f
// vsrc[f*3+h] += Wgat[h,c,f]*att_src[h,c]  (atomic accumulation over c)
__global__ void k_prep_b16(const float* __restrict__ Wgat, const float* __restrict__ att_src,
                           const float* __restrict__ att_dst){
    int idx = blockIdx.x*blockDim.x + threadIdx.x;
    if (idx >= CD*KDIM) return;
    int c = idx / KDIM, k = idx % KDIM;
    int h = k / CD, f = k % CD;
    float wv = Wgat[((size_t)(h*CD + c))*CD + f];
    g_B16[idx] = __float2half(wv);
    atomicAdd(&g_vsrc[f*3 + h], wv*att_src[h*CD + c]);
    atomicAdd(&g_vdst[f*3 + h], wv*att_dst[h*CD + c]);
}

// ---------------- fused GRU: input GEMV + recurrence + attention projections ----------
// 256 blocks x 128 threads, each warp handles 8 nodes. All weights in registers.
__global__ void __launch_bounds__(128) k_gru2(const float* __restrict__ x,
                                              const float* __restrict__ Wih,
                                              const float* __restrict__ Whh,
                                              const float* __restrict__ bih,
                                              const float* __restrict__ bhh){
    int tid = threadIdx.x, lane = tid & 31, w = tid >> 5;
    int wg = blockIdx.x*4 + w;           // 0..1023
    float wir[16], wiz[16], win[16];
    float whr[32], whz[32], whn[32];
    #pragma unroll
    for (int d = 0; d < 16; d++){
        wir[d] = Wih[(lane)*16 + d];
        wiz[d] = Wih[(32 + lane)*16 + d];
        win[d] = Wih[(64 + lane)*16 + d];
    }
    #pragma unroll
    for (int k = 0; k < 32; k++){
        whr[k] = Whh[(lane)*32 + k];
        whz[k] = Whh[(32 + lane)*32 + k];
        whn[k] = Whh[(64 + lane)*32 + k];
    }
    float br = bih[lane] + bhh[lane];
    float bz = bih[32+lane] + bhh[32+lane];
    float bni = bih[64+lane];
    float bnh = bhh[64+lane];

    for (int ni = 0; ni < 8; ni++){
        int n = wg*8 + ni;
        float h = 0.f;
        float s0=0,s1=0,s2=0,d0=0,d1=0,d2=0;
        const float* xrow = x + (size_t)n*TT*DIN;
        float* outp = g_gatin + (size_t)n*CD;
        for (int t = 0; t < TT; t++){
            float xv = (lane < DIN) ? xrow[t*DIN + lane] : 0.f;
            float gr = br, gz = bz, gn = bni;
            #pragma unroll
            for (int d = 0; d < DIN; d++){
                float xd = __shfl_sync(0xffffffffu, xv, d);
                gr += wir[d]*xd; gz += wiz[d]*xd; gn += win[d]*xd;
            }
            float ar = 0.f, az = 0.f, an = 0.f;
            #pragma unroll
            for (int k = 0; k < 32; k++){
                float hk = __shfl_sync(0xffffffffu, h, k);
                ar += whr[k]*hk; az += whz[k]*hk; an += whn[k]*hk;
            }
            float r  = 1.f/(1.f + __expf(-(gr + ar)));
            float z  = 1.f/(1.f + __expf(-(gz + az)));
            float nn = tanhf(gn + r*(an + bnh));
            h = (1.f - z)*nn + z*h;
            outp[t*32 + lane] = h;
            int f = t*32 + lane;
            s0 += h*g_vsrc[f*3+0]; s1 += h*g_vsrc[f*3+1]; s2 += h*g_vsrc[f*3+2];
            d0 += h*g_vdst[f*3+0]; d1 += h*g_vdst[f*3+1]; d2 += h*g_vdst[f*3+2];
        }
        #pragma unroll
        for (int o = 16; o; o >>= 1){
            s0 += __shfl_xor_sync(0xffffffffu, s0, o);
            s1 += __shfl_xor_sync(0xffffffffu, s1, o);
            s2 += __shfl_xor_sync(0xffffffffu, s2, o);
            d0 += __shfl_xor_sync(0xffffffffu, d0, o);
            d1 += __shfl_xor_sync(0xffffffffu, d1, o);
            d2 += __shfl_xor_sync(0xffffffffu, d2, o);
        }
        if (lane == 0){
            g_asrc[n*3+0]=s0; g_asrc[n*3+1]=s1; g_asrc[n*3+2]=s2;
            g_adst[n*3+0]=d0; g_adst[n*3+1]=d1; g_adst[n*3+2]=d2;
        }
    }
}

// ---------------- edge logits + segment max + dst count (fused) ----------------
__global__ void k_elc(const int* __restrict__ ei, const float* __restrict__ ea){
    int e = blockIdx.x*blockDim.x + threadIdx.x;
    if (e >= NE) return;
    int s = ei[e], d = ei[NE + e];
    atomicAdd(&g_count[d], 1);
    float eav = ea[e];
    #pragma unroll
    for (int h = 0; h < HEADS; h++){
        float l = g_asrc[s*3+h] + g_adst[d*3+h] + eav*g_kedge[h];
        l = (l > 0.f) ? l : 0.2f*l;
        g_logit[e*3+h] = l;
        atomicMax(&g_amax[d*3+h], fenc(l));
    }
}

__global__ void k_scan(){
    __shared__ int sh[1024];
    int t = threadIdx.x;
    int loc[8];
    int base = t*8;
    int s = 0;
    #pragma unroll
    for (int i = 0; i < 8; i++){ loc[i] = s; s += g_count[base+i]; }
    sh[t] = s; __syncthreads();
    for (int off = 1; off < 1024; off <<= 1){
        int v = (t >= off) ? sh[t-off] : 0;
        __syncthreads();
        sh[t] += v;
        __syncthreads();
    }
    int excl = (t == 0) ? 0 : sh[t-1];
    #pragma unroll
    for (int i = 0; i < 8; i++){ int o = excl + loc[i]; g_off[base+i] = o; g_cur[base+i] = o; }
    if (t == 1023) g_off[NNODES] = excl + s;
}

// ---------------- scatter + exp + segment sum (fused) ----------------
__global__ void k_scw(const int* __restrict__ ei){
    int e = blockIdx.x*blockDim.x + threadIdx.x;
    if (e >= NE) return;
    int d = ei[NE + e];
    int pos = atomicAdd(&g_cur[d], 1);
    g_sorted[pos] = e;
    #pragma unroll
    for (int h = 0; h < HEADS; h++){
        float w = __expf(g_logit[e*3+h] - fdec(g_amax[d*3+h]));
        g_w[e*3+h] = w;
        atomicAdd(&g_denom[d*3+h], w);
    }
}

// ---------------- aggregation: block per dst node -> fp16 hi/lo split ----------------
__global__ void __launch_bounds__(128) k_agg(const int* __restrict__ ei){
    int n = blockIdx.x;
    int tid = threadIdx.x;
    int s0 = g_off[n], s1 = g_off[n+1];
    float inv0 = (1.f/3.f)/(g_denom[n*3+0] + 1e-16f);
    float inv1 = (1.f/3.f)/(g_denom[n*3+1] + 1e-16f);
    float inv2 = (1.f/3.f)/(g_denom[n*3+2] + 1e-16f);
    float a[3][3] = {};
    for (int i = s0; i < s1; i++){
        int e   = g_sorted[i];
        int src = ei[e];
        float c0 = g_w[e*3+0]*inv0;
        float c1 = g_w[e*3+1]*inv1;
        float c2 = g_w[e*3+2]*inv2;
        const float* xr = g_gatin + (size_t)src*CD;
        float v0 = xr[tid], v1 = xr[tid+128], v2 = xr[tid+256];
        a[0][0] += c0*v0; a[0][1] += c0*v1; a[0][2] += c0*v2;
        a[1][0] += c1*v0; a[1][1] += c1*v1; a[1][2] += c1*v2;
        a[2][0] += c2*v0; a[2][1] += c2*v1; a[2][2] += c2*v2;
    }
    #pragma unroll
    for (int hh = 0; hh < 3; hh++)
        #pragma unroll
        for (int j = 0; j < 3; j++){
            float v = a[hh][j];
            __half hi = __float2half(v);
            __half lo = __float2half(v - __half2float(hi));
            size_t o = (size_t)n*KDIM + hh*CD + tid + 128*j;
            g_Zhi[o] = hi;
            g_Zlo[o] = lo;
        }
}

// ---------------- GEMM via mma.sync fp16 2-product (Z split, B single) ------------------
// out[8192,384] = (Zhi+Zlo)[8192,1152] @ B[384,1152]^T + bias
// CTA tile 128x192 (12 warps, warp tile 32x64), grid (2,64) = 128 CTAs.
// K-chunks of 64, cp.async double-buffered, padded smem rows (72 halves).
#define ROWP    72
#define A_ARR   18432u                // 128*72*2
#define OFF_AHI 0u
#define OFF_ALO 18432u
#define OFF_B   36864u
#define BUF_SZ  64512u                // + 192*72*2
#define GSM_TOT (2u*BUF_SZ)           // 126 KB

__device__ __forceinline__ void gfill(unsigned sb, int tid, int buf, int kc, int m0, int n0){
    unsigned base = sb + (unsigned)buf*BUF_SZ;
    for (int u = tid; u < 3584; u += 384){
        const __half* src;
        unsigned off;
        if (u < 2048){
            int arr = u >> 10, rs = u & 1023, r = rs >> 3, s = rs & 7;
            src = (arr ? g_Zlo : g_Zhi) + (size_t)(m0 + r)*KDIM + kc*64 + s*8;
            off = (unsigned)arr*A_ARR + (unsigned)(r*ROWP + s*8)*2u;
        } else {
            int v = u - 2048;
            int r = v >> 3, s = v & 7;
            src = g_B16 + (size_t)(n0 + r)*KDIM + kc*64 + s*8;
            off = OFF_B + (unsigned)(r*ROWP + s*8)*2u;
        }
        asm volatile("cp.async.ca.shared.global [%0], [%1], 16;"
                     :: "r"(base + off), "l"(src) : "memory");
    }
    asm volatile("cp.async.commit_group;" ::: "memory");
}

__global__ void __launch_bounds__(384, 1) k_gemm_mma(const float* __restrict__ bias){
    extern __shared__ char sm[];
    unsigned sb = smem_u32(sm);
    int tid = threadIdx.x, lane = tid & 31, w = tid >> 5;
    int m0 = blockIdx.y*128, n0 = blockIdx.x*192;
    int wm = (w & 3)*32, wn = (w >> 2)*64;

    float acc[2][8][4];
    #pragma unroll
    for (int i = 0; i < 2; i++)
        #pragma unroll
        for (int j = 0; j < 8; j++)
            #pragma unroll
            for (int q = 0; q < 4; q++) acc[i][j][q] = 0.f;

    gfill(sb, tid, 0, 0, m0, n0);
    for (int kc = 0; kc < 18; kc++){
        if (kc + 1 < 18){
            gfill(sb, tid, (kc+1)&1, kc+1, m0, n0);
            asm volatile("cp.async.wait_group 1;" ::: "memory");
        } else {
            asm volatile("cp.async.wait_group 0;" ::: "memory");
        }
        __syncthreads();
        unsigned base = sb + (unsigned)(kc&1)*BUF_SZ;
        #pragma unroll
        for (int ks = 0; ks < 4; ks++){
            int kk = ks*16;
            unsigned ahi[2][4], alo[2][4];
            #pragma unroll
            for (int mi = 0; mi < 2; mi++){
                int row = wm + mi*16 + (lane & 15);
                int col = kk + 8*(lane >> 4);
                unsigned off = (unsigned)(row*ROWP + col)*2u;
                LDSM4(ahi[mi], base + OFF_AHI + off);
                LDSM4(alo[mi], base + OFF_ALO + off);
            }
            unsigned bb[4][4];
            #pragma unroll
            for (int p = 0; p < 4; p++){
                int row = wn + p*16 + (lane & 7) + 8*(lane >> 4);
                int col = kk + 8*((lane >> 3) & 1);
                unsigned off = (unsigned)(row*ROWP + col)*2u;
                LDSM4(bb[p], base + OFF_B + off);
            }
            #pragma unroll
            for (int mi = 0; mi < 2; mi++)
                #pragma unroll
                for (int nj = 0; nj < 8; nj++){
                    unsigned* bp = &bb[nj>>1][(nj&1)*2];
                    MMAF16(acc[mi][nj], ahi[mi], bp);
                    MMAF16(acc[mi][nj], alo[mi], bp);
                }
        }
        __syncthreads();
    }

    int r0 = lane >> 2, c0 = 2*(lane & 3);
    #pragma unroll
    for (int mi = 0; mi < 2; mi++)
        #pragma unroll
        for (int nj = 0; nj < 8; nj++){
            int row = m0 + wm + mi*16 + r0;
            int col = n0 + wn + nj*8 + c0;
            float b0 = bias[col], b1 = bias[col+1];
            *(float2*)&g_gatout[(size_t)row*CD + col] =
                make_float2(acc[mi][nj][0] + b0, acc[mi][nj][1] + b1);
            *(float2*)&g_gatout[(size_t)(row+8)*CD + col] =
                make_float2(acc[mi][nj][2] + b0, acc[mi][nj][3] + b1);
        }
}

// ---------------- predictor: warp per node ----------------
__global__ void k_pred(const float* __restrict__ Wp1, const float* __restrict__ bp1,
                       const float* __restrict__ Wp3, const float* __restrict__ bp3,
                       float* __restrict__ out){
    int warp = threadIdx.x >> 5, lane = threadIdx.x & 31;
    int n = blockIdx.x*8 + warp;
    const float* row = g_gatout + (size_t)n*CD;
    float w1 = Wp1[lane];
    float b1 = bp1[0];
    float p[TT];
    #pragma unroll
    for (int t = 0; t < TT; t++){
        float s = row[t*HID + lane]*w1;
        #pragma unroll
        for (int o = 16; o; o >>= 1) s += __shfl_xor_sync(0xffffffffu, s, o);
        s += b1;
        p[t] = (s > 0.f) ? s : 0.f;
    }
    if (lane < PLEN){
        float q = bp3[lane];
        #pragma unroll
        for (int t = 0; t < TT; t++) q += p[t]*Wp3[lane*TT + t];
        out[(size_t)n*PLEN + lane] = (q > 0.f) ? q : 0.f;
    }
}

// ---------------- batch max-pool ----------------
__global__ void k_pool(const int* __restrict__ bv){
    int g0 = blockIdx.x*128;
    int c  = threadIdx.x;
    int b  = bv[g0];
    float m = -3.0e38f;
    for (int i = 0; i < 128; i++){
        float v = g_gatout[(size_t)(g0+i)*CD + c];
        m = fmaxf(m, v);
    }
    atomicMax(&g_pooled[b*CD + c], fenc(m));
}

// ---------------- classifier + softmax ----------------
__global__ void k_cls(const float* __restrict__ Wc1, const float* __restrict__ bc1,
                      const float* __restrict__ Wc2, const float* __restrict__ bc2,
                      float* __restrict__ out, int out_size){
    __shared__ float l1[NB][32];
    __shared__ float l2[NB][2];
    int tid = threadIdx.x;
    int b = tid >> 5, i = tid & 31;
    float a = bc1[i];
    for (int c = 0; c < CD; c++) a += fdec(g_pooled[b*CD + c]) * Wc1[i*CD + c];
    l1[b][i] = a;
    __syncthreads();
    if (tid < NB*2){
        int bb = tid >> 1, j = tid & 1;
        float v = bc2[j];
        for (int k = 0; k < 32; k++) v += l1[bb][k]*Wc2[j*32 + k];
        l2[bb][j] = v;
    }
    __syncthreads();
    if (tid < NB*2){
        int bb = tid >> 1, j = tid & 1;
        float m = fmaxf(l2[bb][0], l2[bb][1]);
        float e0 = __expf(l2[bb][0] - m), e1 = __expf(l2[bb][1] - m);
        out[out_size - NB*2 + bb*2 + j] = ((j == 0) ? e0 : e1) / (e0 + e1);
    }
}

// ---------------- launch ----------------
extern "C" void kernel_launch(void* const* d_in, const int* in_sizes, int n_in,
                              void* d_out, int out_size){
    const float* x   = (const float*)d_in[0];
    const int*   ei  = (const int*)  d_in[1];
    const float* ea  = (const float*)d_in[2];
    const int*   bv  = (const int*)  d_in[3];
    int wb = (n_in >= 23 && in_sizes[4] == 1) ? 5 : 4;
    const float* Wih      = (const float*)d_in[wb+0];
    const float* Whh      = (const float*)d_in[wb+1];
    const float* bih      = (const float*)d_in[wb+2];
    const float* bhh      = (const float*)d_in[wb+3];
    const float* Wgat     = (const float*)d_in[wb+4];
    const float* att_src  = (const float*)d_in[wb+5];
    const float* att_dst  = (const float*)d_in[wb+6];
    const float* Wedge    = (const float*)d_in[wb+7];
    const float* att_edge = (const float*)d_in[wb+8];
    const float* gat_bias = (const float*)d_in[wb+9];
    const float* Wp1      = (const float*)d_in[wb+10];
    const float* bp1      = (const float*)d_in[wb+11];
    const float* Wp3      = (const float*)d_in[wb+12];
    const float* bp3      = (const float*)d_in[wb+13];
    const float* Wc1      = (const float*)d_in[wb+14];
    const float* bc1      = (const float*)d_in[wb+15];
    const float* Wc2      = (const float*)d_in[wb+16];
    const float* bc2      = (const float*)d_in[wb+17];
    float* out = (float*)d_out;

    cudaFuncSetAttribute(k_gemm_mma, cudaFuncAttributeMaxDynamicSharedMemorySize, GSM_TOT);

    k_init      <<<96, 256>>>(Wedge, att_edge);
    k_prep_b16  <<<(CD*KDIM + 255)/256, 256>>>(Wgat, att_src, att_dst);
    k_gru2      <<<256, 128>>>(x, Wih, Whh, bih, bhh);
    k_elc       <<<NE/256, 256>>>(ei, ea);
    k_scan      <<<1, 1024>>>();
    k_scw       <<<NE/256, 256>>>(ei);
    k_agg       <<<NNODES, 128>>>(ei);
    k_gemm_mma  <<<dim3(2, 64), 384, GSM_TOT>>>(gat_bias);
    k_pred      <<<1024, 256>>>(Wp1, bp1, Wp3, bp3, out);
    k_pool      <<<64, 384>>>(bv);
    k_cls       <<<1, 256>>>(Wc1, bc1, Wc2, bc2, out, out_size);
}

// round 5
// speedup vs baseline: 1.9620x; 1.1346x over previous
#include <cuda_runtime.h>
#include <cuda_fp16.h>
#include <math.h>

#define NB      8
#define NODE    1024
#define TT      12
#define DIN     16
#define HID     32
#define HEADS   3
#define CD      384
#define NNODES  8192
#define NE      65536
#define PLEN    6
#define KDIM    1152        // HEADS*CD

// ---------------- scratch (static device memory) ----------------
__device__ float    g_gatin [NNODES*CD];
__device__ float    g_vsrc  [CD*HEADS];
__device__ float    g_vdst  [CD*HEADS];
__device__ float    g_kedge [HEADS];
__device__ __half   g_B16   [CD*KDIM];      // B[n][k] row-major fp16
__device__ float    g_asrc  [NNODES*HEADS];
__device__ float    g_adst  [NNODES*HEADS];
__device__ float    g_denom [NNODES*HEADS];
__device__ int      g_count [NNODES];
__device__ int      g_off   [NNODES+1];
__device__ int      g_cur   [NNODES];
__device__ float4   g_ew    [NE];            // (src, w0, w1, w2) sorted by dst
__device__ __half   g_Z16   [NNODES*KDIM];
__device__ float    g_gatout[NNODES*CD];
__device__ unsigned g_pooled[NB*CD];

// order-preserving float <-> uint for atomicMax
__device__ __forceinline__ unsigned fenc(float f){
    unsigned u = __float_as_uint(f);
    return (u & 0x80000000u) ? ~u : (u | 0x80000000u);
}
__device__ __forceinline__ float fdec(unsigned u){
    unsigned v = (u & 0x80000000u) ? (u & 0x7fffffffu) : ~u;
    return __uint_as_float(v);
}

__device__ __forceinline__ unsigned smem_u32(const void* p){
    unsigned a;
    asm("{ .reg .u64 t; cvta.to.shared.u64 t, %1; cvt.u32.u64 %0, t; }" : "=r"(a) : "l"(p));
    return a;
}

// ---------------- mma.sync helpers ----------------
#define LDSM4(r, a)                                                                 \
    asm volatile("ldmatrix.sync.aligned.m8n8.x4.shared.b16 {%0,%1,%2,%3}, [%4];"    \
        : "=r"((r)[0]), "=r"((r)[1]), "=r"((r)[2]), "=r"((r)[3]) : "r"(a))

#define MMAF16(d, a, b)                                                             \
    asm volatile("mma.sync.aligned.m16n8k16.row.col.f32.f16.f16.f32 "               \
        "{%0,%1,%2,%3}, {%4,%5,%6,%7}, {%8,%9}, {%0,%1,%2,%3};"                     \
        : "+f"((d)[0]), "+f"((d)[1]), "+f"((d)[2]), "+f"((d)[3])                    \
        : "r"((a)[0]), "r"((a)[1]), "r"((a)[2]), "r"((a)[3]),                       \
          "r"((b)[0]), "r"((b)[1]))

// ---------------- init: zero scratch + kedge ----------------
__global__ void k_init(const float* __restrict__ Wedge, const float* __restrict__ att_edge){
    int i = blockIdx.x*blockDim.x + threadIdx.x;
    if (i < NNODES) g_count[i] = 0;
    if (i < NNODES*HEADS) g_denom[i] = 0.f;
    if (i < NB*CD) g_pooled[i] = fenc(-3.0e38f);
    if (i < CD*HEADS){ g_vsrc[i] = 0.f; g_vdst[i] = 0.f; }
    if (i < 96){
        int h = i >> 5, lane = i & 31;
        float s = 0.f;
        for (int c = lane; c < CD; c += 32) s += Wedge[h*CD + c]*att_edge[h*CD + c];
        #pragma unroll
        for (int o = 16; o; o >>= 1) s += __shfl_xor_sync(0xffffffffu, s, o);
        if (lane == 0) g_kedge[h] = s;
    }
}

// ---------------- B fp16 + attention projection vectors (fused) ----------------
__global__ void k_prep_b16(const float* __restrict__ Wgat, const float* __restrict__ att_src,
                           const float* __restrict__ att_dst){
    int idx = blockIdx.x*blockDim.x + threadIdx.x;
    if (idx >= CD*KDIM) return;
    int c = idx / KDIM, k = idx % KDIM;
    int h = k / CD, f = k % CD;
    float wv = Wgat[((size_t)(h*CD + c))*CD + f];
    g_B16[idx] = __float2half(wv);
    atomicAdd(&g_vsrc[f*3 + h], wv*att_src[h*CD + c]);
    atomicAdd(&g_vdst[f*3 + h], wv*att_dst[h*CD + c]);
}

// ---------------- fused GRU: input GEMV + recurrence + attention projections ----------
// 512 blocks x 128 threads, each warp handles 4 nodes. All weights in registers.
__global__ void __launch_bounds__(128) k_gru2(const float* __restrict__ x,
                                              const float* __restrict__ Wih,
                                              const float* __restrict__ Whh,
                                              const float* __restrict__ bih,
                                              const float* __restrict__ bhh){
    int tid = threadIdx.x, lane = tid & 31, w = tid >> 5;
    int wg = blockIdx.x*4 + w;           // 0..2047
    float wir[16], wiz[16], win[16];
    float whr[32], whz[32], whn[32];
    #pragma unroll
    for (int d = 0; d < 16; d++){
        wir[d] = Wih[(lane)*16 + d];
        wiz[d] = Wih[(32 + lane)*16 + d];
        win[d] = Wih[(64 + lane)*16 + d];
    }
    #pragma unroll
    for (int k = 0; k < 32; k++){
        whr[k] = Whh[(lane)*32 + k];
        whz[k] = Whh[(32 + lane)*32 + k];
        whn[k] = Whh[(64 + lane)*32 + k];
    }
    float br = bih[lane] + bhh[lane];
    float bz = bih[32+lane] + bhh[32+lane];
    float bni = bih[64+lane];
    float bnh = bhh[64+lane];

    for (int ni = 0; ni < 4; ni++){
        int n = wg*4 + ni;
        float h = 0.f;
        float s0=0,s1=0,s2=0,d0=0,d1=0,d2=0;
        const float* xrow = x + (size_t)n*TT*DIN;
        float* outp = g_gatin + (size_t)n*CD;
        for (int t = 0; t < TT; t++){
            float xv = (lane < DIN) ? xrow[t*DIN + lane] : 0.f;
            float gr = br, gz = bz, gn = bni;
            #pragma unroll
            for (int d = 0; d < DIN; d++){
                float xd = __shfl_sync(0xffffffffu, xv, d);
                gr += wir[d]*xd; gz += wiz[d]*xd; gn += win[d]*xd;
            }
            float ar = 0.f, az = 0.f, an = 0.f;
            #pragma unroll
            for (int k = 0; k < 32; k++){
                float hk = __shfl_sync(0xffffffffu, h, k);
                ar += whr[k]*hk; az += whz[k]*hk; an += whn[k]*hk;
            }
            float r  = 1.f/(1.f + __expf(-(gr + ar)));
            float z  = 1.f/(1.f + __expf(-(gz + az)));
            float nn = tanhf(gn + r*(an + bnh));
            h = (1.f - z)*nn + z*h;
            outp[t*32 + lane] = h;
            int f = t*32 + lane;
            s0 += h*g_vsrc[f*3+0]; s1 += h*g_vsrc[f*3+1]; s2 += h*g_vsrc[f*3+2];
            d0 += h*g_vdst[f*3+0]; d1 += h*g_vdst[f*3+1]; d2 += h*g_vdst[f*3+2];
        }
        #pragma unroll
        for (int o = 16; o; o >>= 1){
            s0 += __shfl_xor_sync(0xffffffffu, s0, o);
            s1 += __shfl_xor_sync(0xffffffffu, s1, o);
            s2 += __shfl_xor_sync(0xffffffffu, s2, o);
            d0 += __shfl_xor_sync(0xffffffffu, d0, o);
            d1 += __shfl_xor_sync(0xffffffffu, d1, o);
            d2 += __shfl_xor_sync(0xffffffffu, d2, o);
        }
        if (lane == 0){
            g_asrc[n*3+0]=s0; g_asrc[n*3+1]=s1; g_asrc[n*3+2]=s2;
            g_adst[n*3+0]=d0; g_adst[n*3+1]=d1; g_adst[n*3+2]=d2;
        }
    }
}

// ---------------- dst histogram ----------------
__global__ void k_count(const int* __restrict__ ei){
    int i = blockIdx.x*blockDim.x + threadIdx.x;
    int4 d = ((const int4*)(ei + NE))[i];
    atomicAdd(&g_count[d.x], 1);
    atomicAdd(&g_count[d.y], 1);
    atomicAdd(&g_count[d.z], 1);
    atomicAdd(&g_count[d.w], 1);
}

__global__ void k_scan(){
    __shared__ int sh[1024];
    int t = threadIdx.x;
    int loc[8];
    int base = t*8;
    int s = 0;
    #pragma unroll
    for (int i = 0; i < 8; i++){ loc[i] = s; s += g_count[base+i]; }
    sh[t] = s; __syncthreads();
    for (int off = 1; off < 1024; off <<= 1){
        int v = (t >= off) ? sh[t-off] : 0;
        __syncthreads();
        sh[t] += v;
        __syncthreads();
    }
    int excl = (t == 0) ? 0 : sh[t-1];
    #pragma unroll
    for (int i = 0; i < 8; i++){ int o = excl + loc[i]; g_off[base+i] = o; g_cur[base+i] = o; }
    if (t == 1023) g_off[NNODES] = excl + s;
}

// ---------------- logits + exp + scatter + denom (fused; no max-shift needed) ----------
__global__ void k_scw(const int* __restrict__ ei, const float* __restrict__ ea){
    int e = blockIdx.x*blockDim.x + threadIdx.x;
    if (e >= NE) return;
    int s = ei[e], d = ei[NE + e];
    float eav = ea[e];
    float w[3];
    #pragma unroll
    for (int h = 0; h < HEADS; h++){
        float l = g_asrc[s*3+h] + g_adst[d*3+h] + eav*g_kedge[h];
        l = (l > 0.f) ? l : 0.2f*l;            // leaky_relu 0.2
        w[h] = __expf(l);                      // logits are O(1): no max-shift needed
        atomicAdd(&g_denom[d*3+h], w[h]);
    }
    int pos = atomicAdd(&g_cur[d], 1);
    g_ew[pos] = make_float4(__int_as_float(s), w[0], w[1], w[2]);
}

// ---------------- aggregation: block per dst node -> fp16 Z ----------------
__global__ void __launch_bounds__(128) k_agg(){
    int n = blockIdx.x;
    int tid = threadIdx.x;
    int s0 = g_off[n], s1 = g_off[n+1];
    float inv0 = (1.f/3.f)/(g_denom[n*3+0] + 1e-16f);
    float inv1 = (1.f/3.f)/(g_denom[n*3+1] + 1e-16f);
    float inv2 = (1.f/3.f)/(g_denom[n*3+2] + 1e-16f);
    float a[3][3] = {};
    #pragma unroll 2
    for (int i = s0; i < s1; i++){
        float4 q = g_ew[i];
        int src = __float_as_int(q.x);
        float c0 = q.y*inv0, c1 = q.z*inv1, c2 = q.w*inv2;
        const float* xr = g_gatin + (size_t)src*CD;
        float v0 = xr[tid], v1 = xr[tid+128], v2 = xr[tid+256];
        a[0][0] += c0*v0; a[0][1] += c0*v1; a[0][2] += c0*v2;
        a[1][0] += c1*v0; a[1][1] += c1*v1; a[1][2] += c1*v2;
        a[2][0] += c2*v0; a[2][1] += c2*v1; a[2][2] += c2*v2;
    }
    #pragma unroll
    for (int hh = 0; hh < 3; hh++)
        #pragma unroll
        for (int j = 0; j < 3; j++)
            g_Z16[(size_t)n*KDIM + hh*CD + tid + 128*j] = __float2half(a[hh][j]);
}

// ---------------- GEMM via mma.sync fp16 single product ---------------------------------
// out[8192,384] = Z[8192,1152] @ B[384,1152]^T + bias
// CTA tile 128x192 (12 warps, warp tile 32x64), grid (2,64) = 128 CTAs.
#define ROWP    72
#define OFF_B   18432u                // 128*72*2
#define BUF_SZ  46080u                // + 192*72*2
#define GSM_TOT (2u*BUF_SZ)           // 90 KB

__device__ __forceinline__ void gfill(unsigned sb, int tid, int buf, int kc, int m0, int n0){
    unsigned base = sb + (unsigned)buf*BUF_SZ;
    for (int u = tid; u < 2560; u += 384){
        const __half* src;
        unsigned off;
        if (u < 1024){
            int r = u >> 3, s = u & 7;
            src = g_Z16 + (size_t)(m0 + r)*KDIM + kc*64 + s*8;
            off = (unsigned)(r*ROWP + s*8)*2u;
        } else {
            int v = u - 1024;
            int r = v >> 3, s = v & 7;
            src = g_B16 + (size_t)(n0 + r)*KDIM + kc*64 + s*8;
            off = OFF_B + (unsigned)(r*ROWP + s*8)*2u;
        }
        asm volatile("cp.async.ca.shared.global [%0], [%1], 16;"
                     :: "r"(base + off), "l"(src) : "memory");
    }
    asm volatile("cp.async.commit_group;" ::: "memory");
}

__global__ void __launch_bounds__(384, 1) k_gemm_mma(const float* __restrict__ bias){
    extern __shared__ char sm[];
    unsigned sb = smem_u32(sm);
    int tid = threadIdx.x, lane = tid & 31, w = tid >> 5;
    int m0 = blockIdx.y*128, n0 = blockIdx.x*192;
    int wm = (w & 3)*32, wn = (w >> 2)*64;

    float acc[2][8][4];
    #pragma unroll
    for (int i = 0; i < 2; i++)
        #pragma unroll
        for (int j = 0; j < 8; j++)
            #pragma unroll
            for (int q = 0; q < 4; q++) acc[i][j][q] = 0.f;

    gfill(sb, tid, 0, 0, m0, n0);
    for (int kc = 0; kc < 18; kc++){
        if (kc + 1 < 18){
            gfill(sb, tid, (kc+1)&1, kc+1, m0, n0);
            asm volatile("cp.async.wait_group 1;" ::: "memory");
        } else {
            asm volatile("cp.async.wait_group 0;" ::: "memory");
        }
        __syncthreads();
        unsigned base = sb + (unsigned)(kc&1)*BUF_SZ;
        #pragma unroll
        for (int ks = 0; ks < 4; ks++){
            int kk = ks*16;
            unsigned aa[2][4];
            #pragma unroll
            for (int mi = 0; mi < 2; mi++){
                int row = wm + mi*16 + (lane & 15);
                int col = kk + 8*(lane >> 4);
                LDSM4(aa[mi], base + (unsigned)(row*ROWP + col)*2u);
            }
            unsigned bb[4][4];
            #pragma unroll
            for (int p = 0; p < 4; p++){
                int row = wn + p*16 + (lane & 7) + 8*(lane >> 4);
                int col = kk + 8*((lane >> 3) & 1);
                LDSM4(bb[p], base + OFF_B + (unsigned)(row*ROWP + col)*2u);
            }
            #pragma unroll
            for (int mi = 0; mi < 2; mi++)
                #pragma unroll
                for (int nj = 0; nj < 8; nj++)
                    MMAF16(acc[mi][nj], aa[mi], (&bb[nj>>1][(nj&1)*2]));
        }
        __syncthreads();
    }

    int r0 = lane >> 2, c0 = 2*(lane & 3);
    #pragma unroll
    for (int mi = 0; mi < 2; mi++)
        #pragma unroll
        for (int nj = 0; nj < 8; nj++){
            int row = m0 + wm + mi*16 + r0;
            int col = n0 + wn + nj*8 + c0;
            float b0 = bias[col], b1 = bias[col+1];
            *(float2*)&g_gatout[(size_t)row*CD + col] =
                make_float2(acc[mi][nj][0] + b0, acc[mi][nj][1] + b1);
            *(float2*)&g_gatout[(size_t)(row+8)*CD + col] =
                make_float2(acc[mi][nj][2] + b0, acc[mi][nj][3] + b1);
        }
}

// ---------------- predictor: warp per node ----------------
__global__ void k_pred(const float* __restrict__ Wp1, const float* __restrict__ bp1,
                       const float* __restrict__ Wp3, const float* __restrict__ bp3,
                       float* __restrict__ out){
    int warp = threadIdx.x >> 5, lane = threadIdx.x & 31;
    int n = blockIdx.x*8 + warp;
    const float* row = g_gatout + (size_t)n*CD;
    float w1 = Wp1[lane];
    float b1 = bp1[0];
    float p[TT];
    #pragma unroll
    for (int t = 0; t < TT; t++){
        float s = row[t*HID + lane]*w1;
        #pragma unroll
        for (int o = 16; o; o >>= 1) s += __shfl_xor_sync(0xffffffffu, s, o);
        s += b1;
        p[t] = (s > 0.f) ? s : 0.f;
    }
    if (lane < PLEN){
        float q = bp3[lane];
        #pragma unroll
        for (int t = 0; t < TT; t++) q += p[t]*Wp3[lane*TT + t];
        out[(size_t)n*PLEN + lane] = (q > 0.f) ? q : 0.f;
    }
}

// ---------------- batch max-pool ----------------
__global__ void k_pool(const int* __restrict__ bv){
    int g0 = blockIdx.x*128;
    int c  = threadIdx.x;
    int b  = bv[g0];
    float m = -3.0e38f;
    for (int i = 0; i < 128; i++){
        float v = g_gatout[(size_t)(g0+i)*CD + c];
        m = fmaxf(m, v);
    }
    atomicMax(&g_pooled[b*CD + c], fenc(m));
}

// ---------------- classifier + softmax ----------------
__global__ void k_cls(const float* __restrict__ Wc1, const float* __restrict__ bc1,
                      const float* __restrict__ Wc2, const float* __restrict__ bc2,
                      float* __restrict__ out, int out_size){
    __shared__ float l1[NB][32];
    __shared__ float l2[NB][2];
    int tid = threadIdx.x;
    int b = tid >> 5, i = tid & 31;
    float a = bc1[i];
    for (int c = 0; c < CD; c++) a += fdec(g_pooled[b*CD + c]) * Wc1[i*CD + c];
    l1[b][i] = a;
    __syncthreads();
    if (tid < NB*2){
        int bb = tid >> 1, j = tid & 1;
        float v = bc2[j];
        for (int k = 0; k < 32; k++) v += l1[bb][k]*Wc2[j*32 + k];
        l2[bb][j] = v;
    }
    __syncthreads();
    if (tid < NB*2){
        int bb = tid >> 1, j = tid & 1;
        float m = fmaxf(l2[bb][0], l2[bb][1]);
        float e0 = __expf(l2[bb][0] - m), e1 = __expf(l2[bb][1] - m);
        out[out_size - NB*2 + bb*2 + j] = ((j == 0) ? e0 : e1) / (e0 + e1);
    }
}

// ---------------- launch ----------------
extern "C" void kernel_launch(void* const* d_in, const int* in_sizes, int n_in,
                              void* d_out, int out_size){
    const float* x   = (const float*)d_in[0];
    const int*   ei  = (const int*)  d_in[1];
    const float* ea  = (const float*)d_in[2];
    const int*   bv  = (const int*)  d_in[3];
    int wb = (n_in >= 23 && in_sizes[4] == 1) ? 5 : 4;
    const float* Wih      = (const float*)d_in[wb+0];
    const float* Whh      = (const float*)d_in[wb+1];
    const float* bih      = (const float*)d_in[wb+2];
    const float* bhh      = (const float*)d_in[wb+3];
    const float* Wgat     = (const float*)d_in[wb+4];
    const float* att_src  = (const float*)d_in[wb+5];
    const float* att_dst  = (const float*)d_in[wb+6];
    const float* Wedge    = (const float*)d_in[wb+7];
    const float* att_edge = (const float*)d_in[wb+8];
    const float* gat_bias = (const float*)d_in[wb+9];
    const float* Wp1      = (const float*)d_in[wb+10];
    const float* bp1      = (const float*)d_in[wb+11];
    const float* Wp3      = (const float*)d_in[wb+12];
    const float* bp3      = (const float*)d_in[wb+13];
    const float* Wc1      = (const float*)d_in[wb+14];
    const float* bc1      = (const float*)d_in[wb+15];
    const float* Wc2      = (const float*)d_in[wb+16];
    const float* bc2      = (const float*)d_in[wb+17];
    float* out = (float*)d_out;

    cudaFuncSetAttribute(k_gemm_mma, cudaFuncAttributeMaxDynamicSharedMemorySize, GSM_TOT);

    k_init      <<<96, 256>>>(Wedge, att_edge);
    k_prep_b16  <<<(CD*KDIM + 255)/256, 256>>>(Wgat, att_src, att_dst);
    k_gru2      <<<512, 128>>>(x, Wih, Whh, bih, bhh);
    k_count     <<<NE/1024, 256>>>(ei);
    k_scan      <<<1, 1024>>>();
    k_scw       <<<NE/256, 256>>>(ei, ea);
    k_agg       <<<NNODES, 128>>>();
    k_gemm_mma  <<<dim3(2, 64), 384, GSM_TOT>>>(gat_bias);
    k_pred      <<<1024, 256>>>(Wp1, bp1, Wp3, bp3, out);
    k_pool      <<<64, 384>>>(bv);
    k_cls       <<<1, 256>>>(Wc1, bc1, Wc2, bc2, out, out_size);
}

// round 7
// speedup vs baseline: 2.0940x; 1.0673x over previous
#include <cuda_runtime.h>
#include <cuda_fp16.h>
#include <math.h>

#define NB      8
#define NODE    1024
#define TT      12
#define DIN     16
#define HID     32
#define HEADS   3
#define CD      384
#define NNODES  8192
#define NE      65536
#define PLEN    6
#define KDIM    1152        // HEADS*CD

// ---------------- scratch (static device memory) ----------------
__device__ float    g_gatin [NNODES*CD];
__device__ float    g_vsrc  [CD*HEADS];
__device__ float    g_vdst  [CD*HEADS];
__device__ float    g_kedge [HEADS];
__device__ __half   g_B16   [CD*KDIM];      // B[n][k] row-major fp16
__device__ float    g_asrc  [NNODES*HEADS];
__device__ float    g_adst  [NNODES*HEADS];
__device__ float    g_denom [NNODES*HEADS];
__device__ int      g_count [NNODES];
__device__ int      g_off   [NNODES+1];
__device__ int      g_cur   [NNODES];
__device__ float4   g_ew    [NE];            // (src, w0, w1, w2) sorted by dst
__device__ __half   g_Z16   [NNODES*KDIM];
__device__ float    g_gatout[NNODES*CD];
__device__ unsigned g_pooled[NB*CD];

// order-preserving float <-> uint for atomicMax
__device__ __forceinline__ unsigned fenc(float f){
    unsigned u = __float_as_uint(f);
    return (u & 0x80000000u) ? ~u : (u | 0x80000000u);
}
__device__ __forceinline__ float fdec(unsigned u){
    unsigned v = (u & 0x80000000u) ? (u & 0x7fffffffu) : ~u;
    return __uint_as_float(v);
}

__device__ __forceinline__ unsigned smem_u32(const void* p){
    unsigned a;
    asm("{ .reg .u64 t; cvta.to.shared.u64 t, %1; cvt.u32.u64 %0, t; }" : "=r"(a) : "l"(p));
    return a;
}

// ---------------- mma.sync helpers ----------------
#define LDSM4(r, a)                                                                 \
    asm volatile("ldmatrix.sync.aligned.m8n8.x4.shared.b16 {%0,%1,%2,%3}, [%4];"    \
        : "=r"((r)[0]), "=r"((r)[1]), "=r"((r)[2]), "=r"((r)[3]) : "r"(a))

#define MMAF16(d, a, b)                                                             \
    asm volatile("mma.sync.aligned.m16n8k16.row.col.f32.f16.f16.f32 "               \
        "{%0,%1,%2,%3}, {%4,%5,%6,%7}, {%8,%9}, {%0,%1,%2,%3};"                     \
        : "+f"((d)[0]), "+f"((d)[1]), "+f"((d)[2]), "+f"((d)[3])                    \
        : "r"((a)[0]), "r"((a)[1]), "r"((a)[2]), "r"((a)[3]),                       \
          "r"((b)[0]), "r"((b)[1]))

// ---------------- init: zero scratch + kedge ----------------
__global__ void k_init(const float* __restrict__ Wedge, const float* __restrict__ att_edge){
    int i = blockIdx.x*blockDim.x + threadIdx.x;
    if (i < NNODES) g_count[i] = 0;
    if (i < NNODES*HEADS) g_denom[i] = 0.f;
    if (i < NB*CD) g_pooled[i] = fenc(-3.0e38f);
    if (i < CD*HEADS){ g_vsrc[i] = 0.f; g_vdst[i] = 0.f; }
    if (i < 96){
        int h = i >> 5, lane = i & 31;
        float s = 0.f;
        for (int c = lane; c < CD; c += 32) s += Wedge[h*CD + c]*att_edge[h*CD + c];
        #pragma unroll
        for (int o = 16; o; o >>= 1) s += __shfl_xor_sync(0xffffffffu, s, o);
        if (lane == 0) g_kedge[h] = s;
    }
}

// ---------------- attention projection vectors (atomic accumulation) ----------------
__global__ void k_vecs(const float* __restrict__ Wgat, const float* __restrict__ att_src,
                       const float* __restrict__ att_dst){
    int idx = blockIdx.x*blockDim.x + threadIdx.x;
    if (idx >= CD*KDIM) return;
    int c = idx / KDIM, k = idx % KDIM;
    int h = k / CD, f = k % CD;
    float wv = Wgat[((size_t)(h*CD + c))*CD + f];
    atomicAdd(&g_vsrc[f*3 + h], wv*att_src[h*CD + c]);
    atomicAdd(&g_vdst[f*3 + h], wv*att_dst[h*CD + c]);
}

// ---------------- B fp16 convert (independent; runs on side stream) ----------------
__global__ void k_b16(const float* __restrict__ Wgat){
    int idx = blockIdx.x*blockDim.x + threadIdx.x;
    if (idx >= CD*KDIM) return;
    int c = idx / KDIM, k = idx % KDIM;
    int h = k / CD, f = k % CD;
    g_B16[idx] = __float2half(Wgat[((size_t)(h*CD + c))*CD + f]);
}

// ---------------- fused GRU: input GEMV + recurrence + attention projections ----------
__global__ void __launch_bounds__(128) k_gru2(const float* __restrict__ x,
                                              const float* __restrict__ Wih,
                                              const float* __restrict__ Whh,
                                              const float* __restrict__ bih,
                                              const float* __restrict__ bhh){
    int tid = threadIdx.x, lane = tid & 31, w = tid >> 5;
    int wg = blockIdx.x*4 + w;           // 0..2047
    float wir[16], wiz[16], win[16];
    float whr[32], whz[32], whn[32];
    #pragma unroll
    for (int d = 0; d < 16; d++){
        wir[d] = Wih[(lane)*16 + d];
        wiz[d] = Wih[(32 + lane)*16 + d];
        win[d] = Wih[(64 + lane)*16 + d];
    }
    #pragma unroll
    for (int k = 0; k < 32; k++){
        whr[k] = Whh[(lane)*32 + k];
        whz[k] = Whh[(32 + lane)*32 + k];
        whn[k] = Whh[(64 + lane)*32 + k];
    }
    float br = bih[lane] + bhh[lane];
    float bz = bih[32+lane] + bhh[32+lane];
    float bni = bih[64+lane];
    float bnh = bhh[64+lane];

    for (int ni = 0; ni < 4; ni++){
        int n = wg*4 + ni;
        float h = 0.f;
        float s0=0,s1=0,s2=0,d0=0,d1=0,d2=0;
        const float* xrow = x + (size_t)n*TT*DIN;
        float* outp = g_gatin + (size_t)n*CD;
        for (int t = 0; t < TT; t++){
            float xv = (lane < DIN) ? xrow[t*DIN + lane] : 0.f;
            float gr = br, gz = bz, gn = bni;
            #pragma unroll
            for (int d = 0; d < DIN; d++){
                float xd = __shfl_sync(0xffffffffu, xv, d);
                gr += wir[d]*xd; gz += wiz[d]*xd; gn += win[d]*xd;
            }
            float ar = 0.f, az = 0.f, an = 0.f;
            #pragma unroll
            for (int k = 0; k < 32; k++){
                float hk = __shfl_sync(0xffffffffu, h, k);
                ar += whr[k]*hk; az += whz[k]*hk; an += whn[k]*hk;
            }
            float r  = 1.f/(1.f + __expf(-(gr + ar)));
            float z  = 1.f/(1.f + __expf(-(gz + az)));
            float nn = tanhf(gn + r*(an + bnh));
            h = (1.f - z)*nn + z*h;
            outp[t*32 + lane] = h;
            int f = t*32 + lane;
            s0 += h*g_vsrc[f*3+0]; s1 += h*g_vsrc[f*3+1]; s2 += h*g_vsrc[f*3+2];
            d0 += h*g_vdst[f*3+0]; d1 += h*g_vdst[f*3+1]; d2 += h*g_vdst[f*3+2];
        }
        #pragma unroll
        for (int o = 16; o; o >>= 1){
            s0 += __shfl_xor_sync(0xffffffffu, s0, o);
            s1 += __shfl_xor_sync(0xffffffffu, s1, o);
            s2 += __shfl_xor_sync(0xffffffffu, s2, o);
            d0 += __shfl_xor_sync(0xffffffffu, d0, o);
            d1 += __shfl_xor_sync(0xffffffffu, d1, o);
            d2 += __shfl_xor_sync(0xffffffffu, d2, o);
        }
        if (lane == 0){
            g_asrc[n*3+0]=s0; g_asrc[n*3+1]=s1; g_asrc[n*3+2]=s2;
            g_adst[n*3+0]=d0; g_adst[n*3+1]=d1; g_adst[n*3+2]=d2;
        }
    }
}

// ---------------- dst histogram ----------------
__global__ void k_count(const int* __restrict__ ei){
    int i = blockIdx.x*blockDim.x + threadIdx.x;
    int4 d = ((const int4*)(ei + NE))[i];
    atomicAdd(&g_count[d.x], 1);
    atomicAdd(&g_count[d.y], 1);
    atomicAdd(&g_count[d.z], 1);
    atomicAdd(&g_count[d.w], 1);
}

__global__ void k_scan(){
    __shared__ int sh[1024];
    int t = threadIdx.x;
    int loc[8];
    int base = t*8;
    int s = 0;
    #pragma unroll
    for (int i = 0; i < 8; i++){ loc[i] = s; s += g_count[base+i]; }
    sh[t] = s; __syncthreads();
    for (int off = 1; off < 1024; off <<= 1){
        int v = (t >= off) ? sh[t-off] : 0;
        __syncthreads();
        sh[t] += v;
        __syncthreads();
    }
    int excl = (t == 0) ? 0 : sh[t-1];
    #pragma unroll
    for (int i = 0; i < 8; i++){ int o = excl + loc[i]; g_off[base+i] = o; g_cur[base+i] = o; }
    if (t == 1023) g_off[NNODES] = excl + s;
}

// ---------------- logits + exp + scatter + denom (fused) ----------
__global__ void k_scw(const int* __restrict__ ei, const float* __restrict__ ea){
    int e = blockIdx.x*blockDim.x + threadIdx.x;
    if (e >= NE) return;
    int s = ei[e], d = ei[NE + e];
    float eav = ea[e];
    float w[3];
    #pragma unroll
    for (int h = 0; h < HEADS; h++){
        float l = g_asrc[s*3+h] + g_adst[d*3+h] + eav*g_kedge[h];
        l = (l > 0.f) ? l : 0.2f*l;            // leaky_relu 0.2
        w[h] = __expf(l);                      // logits are O(1): no max-shift needed
        atomicAdd(&g_denom[d*3+h], w[h]);
    }
    int pos = atomicAdd(&g_cur[d], 1);
    g_ew[pos] = make_float4(__int_as_float(s), w[0], w[1], w[2]);
}

// ---------------- aggregation: block per dst node -> fp16 Z ----------------
__global__ void __launch_bounds__(128) k_agg(){
    int n = blockIdx.x;
    int tid = threadIdx.x;
    int s0 = g_off[n], s1 = g_off[n+1];
    float inv0 = (1.f/3.f)/(g_denom[n*3+0] + 1e-16f);
    float inv1 = (1.f/3.f)/(g_denom[n*3+1] + 1e-16f);
    float inv2 = (1.f/3.f)/(g_denom[n*3+2] + 1e-16f);
    float a[3][3] = {};
    #pragma unroll 2
    for (int i = s0; i < s1; i++){
        float4 q = g_ew[i];
        int src = __float_as_int(q.x);
        float c0 = q.y*inv0, c1 = q.z*inv1, c2 = q.w*inv2;
        const float* xr = g_gatin + (size_t)src*CD;
        float v0 = xr[tid], v1 = xr[tid+128], v2 = xr[tid+256];
        a[0][0] += c0*v0; a[0][1] += c0*v1; a[0][2] += c0*v2;
        a[1][0] += c1*v0; a[1][1] += c1*v1; a[1][2] += c1*v2;
        a[2][0] += c2*v0; a[2][1] += c2*v1; a[2][2] += c2*v2;
    }
    #pragma unroll
    for (int hh = 0; hh < 3; hh++)
        #pragma unroll
        for (int j = 0; j < 3; j++)
            g_Z16[(size_t)n*KDIM + hh*CD + tid + 128*j] = __float2half(a[hh][j]);
}

// ---------------- GEMM via mma.sync fp16 ----------------
#define ROWP    72
#define OFF_B   18432u                // 128*72*2
#define BUF_SZ  46080u                // + 192*72*2
#define GSM_TOT (2u*BUF_SZ)           // 90 KB

__device__ __forceinline__ void gfill(unsigned sb, int tid, int buf, int kc, int m0, int n0){
    unsigned base = sb + (unsigned)buf*BUF_SZ;
    for (int u = tid; u < 2560; u += 384){
        const __half* src;
        unsigned off;
        if (u < 1024){
            int r = u >> 3, s = u & 7;
            src = g_Z16 + (size_t)(m0 + r)*KDIM + kc*64 + s*8;
            off = (unsigned)(r*ROWP + s*8)*2u;
        } else {
            int v = u - 1024;
            int r = v >> 3, s = v & 7;
            src = g_B16 + (size_t)(n0 + r)*KDIM + kc*64 + s*8;
            off = OFF_B + (unsigned)(r*ROWP + s*8)*2u;
        }
        asm volatile("cp.async.ca.shared.global [%0], [%1], 16;"
                     :: "r"(base + off), "l"(src) : "memory");
    }
    asm volatile("cp.async.commit_group;" ::: "memory");
}

__global__ void __launch_bounds__(384, 1) k_gemm_mma(const float* __restrict__ bias){
    extern __shared__ char sm[];
    unsigned sb = smem_u32(sm);
    int tid = threadIdx.x, lane = tid & 31, w = tid >> 5;
    int m0 = blockIdx.y*128, n0 = blockIdx.x*192;
    int wm = (w & 3)*32, wn = (w >> 2)*64;

    float acc[2][8][4];
    #pragma unroll
    for (int i = 0; i < 2; i++)
        #pragma unroll
        for (int j = 0; j < 8; j++)
            #pragma unroll
            for (int q = 0; q < 4; q++) acc[i][j][q] = 0.f;

    gfill(sb, tid, 0, 0, m0, n0);
    for (int kc = 0; kc < 18; kc++){
        if (kc + 1 < 18){
            gfill(sb, tid, (kc+1)&1, kc+1, m0, n0);
            asm volatile("cp.async.wait_group 1;" ::: "memory");
        } else {
            asm volatile("cp.async.wait_group 0;" ::: "memory");
        }
        __syncthreads();
        unsigned base = sb + (unsigned)(kc&1)*BUF_SZ;
        #pragma unroll
        for (int ks = 0; ks < 4; ks++){
            int kk = ks*16;
            unsigned aa[2][4];
            #pragma unroll
            for (int mi = 0; mi < 2; mi++){
                int row = wm + mi*16 + (lane & 15);
                int col = kk + 8*(lane >> 4);
                LDSM4(aa[mi], base + (unsigned)(row*ROWP + col)*2u);
            }
            unsigned bb[4][4];
            #pragma unroll
            for (int p = 0; p < 4; p++){
                int row = wn + p*16 + (lane & 7) + 8*(lane >> 4);
                int col = kk + 8*((lane >> 3) & 1);
                LDSM4(bb[p], base + OFF_B + (unsigned)(row*ROWP + col)*2u);
            }
            #pragma unroll
            for (int mi = 0; mi < 2; mi++)
                #pragma unroll
                for (int nj = 0; nj < 8; nj++)
                    MMAF16(acc[mi][nj], aa[mi], (&bb[nj>>1][(nj&1)*2]));
        }
        __syncthreads();
    }

    int r0 = lane >> 2, c0 = 2*(lane & 3);
    #pragma unroll
    for (int mi = 0; mi < 2; mi++)
        #pragma unroll
        for (int nj = 0; nj < 8; nj++){
            int row = m0 + wm + mi*16 + r0;
            int col = n0 + wn + nj*8 + c0;
            float b0 = bias[col], b1 = bias[col+1];
            *(float2*)&g_gatout[(size_t)row*CD + col] =
                make_float2(acc[mi][nj][0] + b0, acc[mi][nj][1] + b1);
            *(float2*)&g_gatout[(size_t)(row+8)*CD + col] =
                make_float2(acc[mi][nj][2] + b0, acc[mi][nj][3] + b1);
        }
}

// ---------------- predictor: warp per node ----------------
__global__ void k_pred(const float* __restrict__ Wp1, const float* __restrict__ bp1,
                       const float* __restrict__ Wp3, const float* __restrict__ bp3,
                       float* __restrict__ out){
    int warp = threadIdx.x >> 5, lane = threadIdx.x & 31;
    int n = blockIdx.x*8 + warp;
    const float* row = g_gatout + (size_t)n*CD;
    float w1 = Wp1[lane];
    float b1 = bp1[0];
    float p[TT];
    #pragma unroll
    for (int t = 0; t < TT; t++){
        float s = row[t*HID + lane]*w1;
        #pragma unroll
        for (int o = 16; o; o >>= 1) s += __shfl_xor_sync(0xffffffffu, s, o);
        s += b1;
        p[t] = (s > 0.f) ? s : 0.f;
    }
    if (lane < PLEN){
        float q = bp3[lane];
        #pragma unroll
        for (int t = 0; t < TT; t++) q += p[t]*Wp3[lane*TT + t];
        out[(size_t)n*PLEN + lane] = (q > 0.f) ? q : 0.f;
    }
}

// ---------------- batch max-pool ----------------
__global__ void k_pool(const int* __restrict__ bv){
    int g0 = blockIdx.x*128;
    int c  = threadIdx.x;
    int b  = bv[g0];
    float m = -3.0e38f;
    for (int i = 0; i < 128; i++){
        float v = g_gatout[(size_t)(g0+i)*CD + c];
        m = fmaxf(m, v);
    }
    atomicMax(&g_pooled[b*CD + c], fenc(m));
}

// ---------------- classifier + softmax ----------------
__global__ void k_cls(const float* __restrict__ Wc1, const float* __restrict__ bc1,
                      const float* __restrict__ Wc2, const float* __restrict__ bc2,
                      float* __restrict__ out, int out_size){
    __shared__ float l1[NB][32];
    __shared__ float l2[NB][2];
    int tid = threadIdx.x;
    int b = tid >> 5, i = tid & 31;
    float a = bc1[i];
    for (int c = 0; c < CD; c++) a += fdec(g_pooled[b*CD + c]) * Wc1[i*CD + c];
    l1[b][i] = a;
    __syncthreads();
    if (tid < NB*2){
        int bb = tid >> 1, j = tid & 1;
        float v = bc2[j];
        for (int k = 0; k < 32; k++) v += l1[bb][k]*Wc2[j*32 + k];
        l2[bb][j] = v;
    }
    __syncthreads();
    if (tid < NB*2){
        int bb = tid >> 1, j = tid & 1;
        float m = fmaxf(l2[bb][0], l2[bb][1]);
        float e0 = __expf(l2[bb][0] - m), e1 = __expf(l2[bb][1] - m);
        out[out_size - NB*2 + bb*2 + j] = ((j == 0) ? e0 : e1) / (e0 + e1);
    }
}

// ---------------- launch: forked-stream graph (all side streams fork from evInit) -------
extern "C" void kernel_launch(void* const* d_in, const int* in_sizes, int n_in,
                              void* d_out, int out_size){
    const float* x   = (const float*)d_in[0];
    const int*   ei  = (const int*)  d_in[1];
    const float* ea  = (const float*)d_in[2];
    const int*   bv  = (const int*)  d_in[3];
    int wb = (n_in >= 23 && in_sizes[4] == 1) ? 5 : 4;
    const float* Wih      = (const float*)d_in[wb+0];
    const float* Whh      = (const float*)d_in[wb+1];
    const float* bih      = (const float*)d_in[wb+2];
    const float* bhh      = (const float*)d_in[wb+3];
    const float* Wgat     = (const float*)d_in[wb+4];
    const float* att_src  = (const float*)d_in[wb+5];
    const float* att_dst  = (const float*)d_in[wb+6];
    const float* Wedge    = (const float*)d_in[wb+7];
    const float* att_edge = (const float*)d_in[wb+8];
    const float* gat_bias = (const float*)d_in[wb+9];
    const float* Wp1      = (const float*)d_in[wb+10];
    const float* bp1      = (const float*)d_in[wb+11];
    const float* Wp3      = (const float*)d_in[wb+12];
    const float* bp3      = (const float*)d_in[wb+13];
    const float* Wc1      = (const float*)d_in[wb+14];
    const float* bc1      = (const float*)d_in[wb+15];
    const float* Wc2      = (const float*)d_in[wb+16];
    const float* bc2      = (const float*)d_in[wb+17];
    float* out = (float*)d_out;

    static cudaStream_t s2 = 0, s3 = 0;
    static cudaEvent_t evInit = 0, evScan = 0, evB16 = 0, evGemm = 0, evCls = 0;
    if (!s2){
        cudaStreamCreateWithFlags(&s2, cudaStreamNonBlocking);
        cudaStreamCreateWithFlags(&s3, cudaStreamNonBlocking);
        cudaEventCreateWithFlags(&evInit, cudaEventDisableTiming);
        cudaEventCreateWithFlags(&evScan, cudaEventDisableTiming);
        cudaEventCreateWithFlags(&evB16,  cudaEventDisableTiming);
        cudaEventCreateWithFlags(&evGemm, cudaEventDisableTiming);
        cudaEventCreateWithFlags(&evCls,  cudaEventDisableTiming);
        cudaFuncSetAttribute(k_gemm_mma, cudaFuncAttributeMaxDynamicSharedMemorySize, GSM_TOT);
    }

    // main chain
    k_init <<<96, 256>>>(Wedge, att_edge);
    cudaEventRecord(evInit, 0);

    // side chain A: edge histogram + scan (forks from evInit)
    cudaStreamWaitEvent(s2, evInit, 0);
    k_count<<<NE/1024, 256, 0, s2>>>(ei);
    k_scan <<<1, 1024, 0, s2>>>();
    cudaEventRecord(evScan, s2);

    // side chain B: fp16 weight conversion (MUST fork from a captured stream too)
    cudaStreamWaitEvent(s3, evInit, 0);
    k_b16  <<<(CD*KDIM + 255)/256, 256, 0, s3>>>(Wgat);
    cudaEventRecord(evB16, s3);

    // main chain continues
    k_vecs <<<(CD*KDIM + 255)/256, 256>>>(Wgat, att_src, att_dst);
    k_gru2 <<<512, 128>>>(x, Wih, Whh, bih, bhh);
    cudaStreamWaitEvent(0, evScan, 0);
    k_scw  <<<NE/256, 256>>>(ei, ea);
    k_agg  <<<NNODES, 128>>>();
    cudaStreamWaitEvent(0, evB16, 0);
    k_gemm_mma<<<dim3(2, 64), 384, GSM_TOT>>>(gat_bias);
    cudaEventRecord(evGemm, 0);

    // epilogue: pred on main, pool+cls on s2, join at end
    cudaStreamWaitEvent(s2, evGemm, 0);
    k_pool <<<64, 384, 0, s2>>>(bv);
    k_cls  <<<1, 256, 0, s2>>>(Wc1, bc1, Wc2, bc2, out, out_size);
    cudaEventRecord(evCls, s2);

    k_pred <<<1024, 256>>>(Wp1, bp1, Wp3, bp3, out);
    cudaStreamWaitEvent(0, evCls, 0);
}

// round 8
// speedup vs baseline: 2.1454x; 1.0245x over previous
#include <cuda_runtime.h>
#include <cuda_fp16.h>
#include <math.h>

#define NB      8
#define NODE    1024
#define TT      12
#define DIN     16
#define HID     32
#define HEADS   3
#define CD      384
#define NNODES  8192
#define NE      65536
#define PLEN    6
#define KDIM    1152        // HEADS*CD

// ---------------- scratch (static device memory) ----------------
__device__ float    g_gatin [NNODES*CD];
__device__ float    g_vsrc  [CD*HEADS];
__device__ float    g_vdst  [CD*HEADS];
__device__ float    g_kedge [HEADS];
__device__ __half   g_B16   [CD*KDIM];      // B[n][k] row-major fp16
__device__ float    g_asrc  [NNODES*HEADS];
__device__ float    g_adst  [NNODES*HEADS];
__device__ float    g_denom [NNODES*HEADS];
__device__ int      g_count [NNODES];
__device__ int      g_off   [NNODES+1];
__device__ int      g_cur   [NNODES];
__device__ float4   g_ew    [NE];            // (src, w0, w1, w2) sorted by dst
__device__ __half   g_Z16   [NNODES*KDIM];
__device__ float    g_gatout[NNODES*CD];
__device__ unsigned g_pooled[NB*CD];

// order-preserving float <-> uint for atomicMax
__device__ __forceinline__ unsigned fenc(float f){
    unsigned u = __float_as_uint(f);
    return (u & 0x80000000u) ? ~u : (u | 0x80000000u);
}
__device__ __forceinline__ float fdec(unsigned u){
    unsigned v = (u & 0x80000000u) ? (u & 0x7fffffffu) : ~u;
    return __uint_as_float(v);
}

__device__ __forceinline__ unsigned smem_u32(const void* p){
    unsigned a;
    asm("{ .reg .u64 t; cvta.to.shared.u64 t, %1; cvt.u32.u64 %0, t; }" : "=r"(a) : "l"(p));
    return a;
}

// ---------------- mma.sync helpers ----------------
#define LDSM4(r, a)                                                                 \
    asm volatile("ldmatrix.sync.aligned.m8n8.x4.shared.b16 {%0,%1,%2,%3}, [%4];"    \
        : "=r"((r)[0]), "=r"((r)[1]), "=r"((r)[2]), "=r"((r)[3]) : "r"(a))

#define MMAF16(d, a, b)                                                             \
    asm volatile("mma.sync.aligned.m16n8k16.row.col.f32.f16.f16.f32 "               \
        "{%0,%1,%2,%3}, {%4,%5,%6,%7}, {%8,%9}, {%0,%1,%2,%3};"                     \
        : "+f"((d)[0]), "+f"((d)[1]), "+f"((d)[2]), "+f"((d)[3])                    \
        : "r"((a)[0]), "r"((a)[1]), "r"((a)[2]), "r"((a)[3]),                       \
          "r"((b)[0]), "r"((b)[1]))

// ---------------- init: zero scratch + kedge (vsrc/vdst now owned by k_vecs_r!) --------
__global__ void k_init(const float* __restrict__ Wedge, const float* __restrict__ att_edge){
    int i = blockIdx.x*blockDim.x + threadIdx.x;
    if (i < NNODES) g_count[i] = 0;
    if (i < NNODES*HEADS) g_denom[i] = 0.f;
    if (i < NB*CD) g_pooled[i] = fenc(-3.0e38f);
    if (i < 96){
        int h = i >> 5, lane = i & 31;
        float s = 0.f;
        for (int c = lane; c < CD; c += 32) s += Wedge[h*CD + c]*att_edge[h*CD + c];
        #pragma unroll
        for (int o = 16; o; o >>= 1) s += __shfl_xor_sync(0xffffffffu, s, o);
        if (lane == 0) g_kedge[h] = s;
    }
}

// ---------------- attention projection vectors: deterministic, no atomics, no deps -----
// grid (12, 3): h = blockIdx.y, f-chunk of 32. 8 warps split the c loop, smem reduce.
__global__ void __launch_bounds__(256) k_vecs_r(const float* __restrict__ Wgat,
                                                const float* __restrict__ att_src,
                                                const float* __restrict__ att_dst){
    __shared__ float ss[8][32], sd[8][32];
    int h = blockIdx.y, f0 = blockIdx.x*32;
    int lane = threadIdx.x & 31, cp = threadIdx.x >> 5;
    float as_ = 0.f, ad_ = 0.f;
    for (int c = cp; c < CD; c += 8){
        float wv = Wgat[((size_t)(h*CD + c))*CD + f0 + lane];
        as_ += wv * att_src[h*CD + c];
        ad_ += wv * att_dst[h*CD + c];
    }
    ss[cp][lane] = as_; sd[cp][lane] = ad_;
    __syncthreads();
    if (cp == 0){
        float s = 0.f, d = 0.f;
        #pragma unroll
        for (int i = 0; i < 8; i++){ s += ss[i][lane]; d += sd[i][lane]; }
        g_vsrc[(f0 + lane)*3 + h] = s;
        g_vdst[(f0 + lane)*3 + h] = d;
    }
}

// ---------------- B fp16 convert (side stream) ----------------
__global__ void k_b16(const float* __restrict__ Wgat){
    int idx = blockIdx.x*blockDim.x + threadIdx.x;
    if (idx >= CD*KDIM) return;
    int c = idx / KDIM, k = idx % KDIM;
    int h = k / CD, f = k % CD;
    g_B16[idx] = __float2half(Wgat[((size_t)(h*CD + c))*CD + f]);
}

// ---------------- fused GRU: input GEMV + recurrence + attention projections ----------
__global__ void __launch_bounds__(128) k_gru2(const float* __restrict__ x,
                                              const float* __restrict__ Wih,
                                              const float* __restrict__ Whh,
                                              const float* __restrict__ bih,
                                              const float* __restrict__ bhh){
    int tid = threadIdx.x, lane = tid & 31, w = tid >> 5;
    int wg = blockIdx.x*4 + w;           // 0..2047
    float wir[16], wiz[16], win[16];
    float whr[32], whz[32], whn[32];
    #pragma unroll
    for (int d = 0; d < 16; d++){
        wir[d] = Wih[(lane)*16 + d];
        wiz[d] = Wih[(32 + lane)*16 + d];
        win[d] = Wih[(64 + lane)*16 + d];
    }
    #pragma unroll
    for (int k = 0; k < 32; k++){
        whr[k] = Whh[(lane)*32 + k];
        whz[k] = Whh[(32 + lane)*32 + k];
        whn[k] = Whh[(64 + lane)*32 + k];
    }
    float br = bih[lane] + bhh[lane];
    float bz = bih[32+lane] + bhh[32+lane];
    float bni = bih[64+lane];
    float bnh = bhh[64+lane];

    for (int ni = 0; ni < 4; ni++){
        int n = wg*4 + ni;
        float h = 0.f;
        float s0=0,s1=0,s2=0,d0=0,d1=0,d2=0;
        const float* xrow = x + (size_t)n*TT*DIN;
        float* outp = g_gatin + (size_t)n*CD;
        for (int t = 0; t < TT; t++){
            float xv = (lane < DIN) ? xrow[t*DIN + lane] : 0.f;
            float gr = br, gz = bz, gn = bni;
            #pragma unroll
            for (int d = 0; d < DIN; d++){
                float xd = __shfl_sync(0xffffffffu, xv, d);
                gr += wir[d]*xd; gz += wiz[d]*xd; gn += win[d]*xd;
            }
            float ar = 0.f, az = 0.f, an = 0.f;
            #pragma unroll
            for (int k = 0; k < 32; k++){
                float hk = __shfl_sync(0xffffffffu, h, k);
                ar += whr[k]*hk; az += whz[k]*hk; an += whn[k]*hk;
            }
            float r  = 1.f/(1.f + __expf(-(gr + ar)));
            float z  = 1.f/(1.f + __expf(-(gz + az)));
            float nn = tanhf(gn + r*(an + bnh));
            h = (1.f - z)*nn + z*h;
            outp[t*32 + lane] = h;
            int f = t*32 + lane;
            s0 += h*g_vsrc[f*3+0]; s1 += h*g_vsrc[f*3+1]; s2 += h*g_vsrc[f*3+2];
            d0 += h*g_vdst[f*3+0]; d1 += h*g_vdst[f*3+1]; d2 += h*g_vdst[f*3+2];
        }
        #pragma unroll
        for (int o = 16; o; o >>= 1){
            s0 += __shfl_xor_sync(0xffffffffu, s0, o);
            s1 += __shfl_xor_sync(0xffffffffu, s1, o);
            s2 += __shfl_xor_sync(0xffffffffu, s2, o);
            d0 += __shfl_xor_sync(0xffffffffu, d0, o);
            d1 += __shfl_xor_sync(0xffffffffu, d1, o);
            d2 += __shfl_xor_sync(0xffffffffu, d2, o);
        }
        if (lane == 0){
            g_asrc[n*3+0]=s0; g_asrc[n*3+1]=s1; g_asrc[n*3+2]=s2;
            g_adst[n*3+0]=d0; g_adst[n*3+1]=d1; g_adst[n*3+2]=d2;
        }
    }
}

// ---------------- dst histogram ----------------
__global__ void k_count(const int* __restrict__ ei){
    int i = blockIdx.x*blockDim.x + threadIdx.x;
    int4 d = ((const int4*)(ei + NE))[i];
    atomicAdd(&g_count[d.x], 1);
    atomicAdd(&g_count[d.y], 1);
    atomicAdd(&g_count[d.z], 1);
    atomicAdd(&g_count[d.w], 1);
}

__global__ void k_scan(){
    __shared__ int sh[1024];
    int t = threadIdx.x;
    int loc[8];
    int base = t*8;
    int s = 0;
    #pragma unroll
    for (int i = 0; i < 8; i++){ loc[i] = s; s += g_count[base+i]; }
    sh[t] = s; __syncthreads();
    for (int off = 1; off < 1024; off <<= 1){
        int v = (t >= off) ? sh[t-off] : 0;
        __syncthreads();
        sh[t] += v;
        __syncthreads();
    }
    int excl = (t == 0) ? 0 : sh[t-1];
    #pragma unroll
    for (int i = 0; i < 8; i++){ int o = excl + loc[i]; g_off[base+i] = o; g_cur[base+i] = o; }
    if (t == 1023) g_off[NNODES] = excl + s;
}

// ---------------- logits + exp + scatter + denom (fused) ----------
__global__ void k_scw(const int* __restrict__ ei, const float* __restrict__ ea){
    int e = blockIdx.x*blockDim.x + threadIdx.x;
    if (e >= NE) return;
    int s = ei[e], d = ei[NE + e];
    float eav = ea[e];
    float w[3];
    #pragma unroll
    for (int h = 0; h < HEADS; h++){
        float l = g_asrc[s*3+h] + g_adst[d*3+h] + eav*g_kedge[h];
        l = (l > 0.f) ? l : 0.2f*l;            // leaky_relu 0.2
        w[h] = __expf(l);                      // logits are O(1): no max-shift needed
        atomicAdd(&g_denom[d*3+h], w[h]);
    }
    int pos = atomicAdd(&g_cur[d], 1);
    g_ew[pos] = make_float4(__int_as_float(s), w[0], w[1], w[2]);
}

// ---------------- aggregation: block per dst node -> fp16 Z (node range param) ---------
__global__ void __launch_bounds__(128) k_agg(int nbase){
    int n = blockIdx.x + nbase;
    int tid = threadIdx.x;
    int s0 = g_off[n], s1 = g_off[n+1];
    float inv0 = (1.f/3.f)/(g_denom[n*3+0] + 1e-16f);
    float inv1 = (1.f/3.f)/(g_denom[n*3+1] + 1e-16f);
    float inv2 = (1.f/3.f)/(g_denom[n*3+2] + 1e-16f);
    float a[3][3] = {};
    #pragma unroll 2
    for (int i = s0; i < s1; i++){
        float4 q = g_ew[i];
        int src = __float_as_int(q.x);
        float c0 = q.y*inv0, c1 = q.z*inv1, c2 = q.w*inv2;
        const float* xr = g_gatin + (size_t)src*CD;
        float v0 = xr[tid], v1 = xr[tid+128], v2 = xr[tid+256];
        a[0][0] += c0*v0; a[0][1] += c0*v1; a[0][2] += c0*v2;
        a[1][0] += c1*v0; a[1][1] += c1*v1; a[1][2] += c1*v2;
        a[2][0] += c2*v0; a[2][1] += c2*v1; a[2][2] += c2*v2;
    }
    #pragma unroll
    for (int hh = 0; hh < 3; hh++)
        #pragma unroll
        for (int j = 0; j < 3; j++)
            g_Z16[(size_t)n*KDIM + hh*CD + tid + 128*j] = __float2half(a[hh][j]);
}

// ---------------- GEMM via mma.sync fp16 (M-tile range param) ----------------
#define ROWP    72
#define OFF_B   18432u                // 128*72*2
#define BUF_SZ  46080u                // + 192*72*2
#define GSM_TOT (2u*BUF_SZ)           // 90 KB

__device__ __forceinline__ void gfill(unsigned sb, int tid, int buf, int kc, int m0, int n0){
    unsigned base = sb + (unsigned)buf*BUF_SZ;
    for (int u = tid; u < 2560; u += 384){
        const __half* src;
        unsigned off;
        if (u < 1024){
            int r = u >> 3, s = u & 7;
            src = g_Z16 + (size_t)(m0 + r)*KDIM + kc*64 + s*8;
            off = (unsigned)(r*ROWP + s*8)*2u;
        } else {
            int v = u - 1024;
            int r = v >> 3, s = v & 7;
            src = g_B16 + (size_t)(n0 + r)*KDIM + kc*64 + s*8;
            off = OFF_B + (unsigned)(r*ROWP + s*8)*2u;
        }
        asm volatile("cp.async.ca.shared.global [%0], [%1], 16;"
                     :: "r"(base + off), "l"(src) : "memory");
    }
    asm volatile("cp.async.commit_group;" ::: "memory");
}

__global__ void __launch_bounds__(384, 1) k_gemm_mma(const float* __restrict__ bias, int ybase){
    extern __shared__ char sm[];
    unsigned sb = smem_u32(sm);
    int tid = threadIdx.x, lane = tid & 31, w = tid >> 5;
    int m0 = (blockIdx.y + ybase)*128, n0 = blockIdx.x*192;
    int wm = (w & 3)*32, wn = (w >> 2)*64;

    float acc[2][8][4];
    #pragma unroll
    for (int i = 0; i < 2; i++)
        #pragma unroll
        for (int j = 0; j < 8; j++)
            #pragma unroll
            for (int q = 0; q < 4; q++) acc[i][j][q] = 0.f;

    gfill(sb, tid, 0, 0, m0, n0);
    for (int kc = 0; kc < 18; kc++){
        if (kc + 1 < 18){
            gfill(sb, tid, (kc+1)&1, kc+1, m0, n0);
            asm volatile("cp.async.wait_group 1;" ::: "memory");
        } else {
            asm volatile("cp.async.wait_group 0;" ::: "memory");
        }
        __syncthreads();
        unsigned base = sb + (unsigned)(kc&1)*BUF_SZ;
        #pragma unroll
        for (int ks = 0; ks < 4; ks++){
            int kk = ks*16;
            unsigned aa[2][4];
            #pragma unroll
            for (int mi = 0; mi < 2; mi++){
                int row = wm + mi*16 + (lane & 15);
                int col = kk + 8*(lane >> 4);
                LDSM4(aa[mi], base + (unsigned)(row*ROWP + col)*2u);
            }
            unsigned bb[4][4];
            #pragma unroll
            for (int p = 0; p < 4; p++){
                int row = wn + p*16 + (lane & 7) + 8*(lane >> 4);
                int col = kk + 8*((lane >> 3) & 1);
                LDSM4(bb[p], base + OFF_B + (unsigned)(row*ROWP + col)*2u);
            }
            #pragma unroll
            for (int mi = 0; mi < 2; mi++)
                #pragma unroll
                for (int nj = 0; nj < 8; nj++)
                    MMAF16(acc[mi][nj], aa[mi], (&bb[nj>>1][(nj&1)*2]));
        }
        __syncthreads();
    }

    int r0 = lane >> 2, c0 = 2*(lane & 3);
    #pragma unroll
    for (int mi = 0; mi < 2; mi++)
        #pragma unroll
        for (int nj = 0; nj < 8; nj++){
            int row = m0 + wm + mi*16 + r0;
            int col = n0 + wn + nj*8 + c0;
            float b0 = bias[col], b1 = bias[col+1];
            *(float2*)&g_gatout[(size_t)row*CD + col] =
                make_float2(acc[mi][nj][0] + b0, acc[mi][nj][1] + b1);
            *(float2*)&g_gatout[(size_t)(row+8)*CD + col] =
                make_float2(acc[mi][nj][2] + b0, acc[mi][nj][3] + b1);
        }
}

// ---------------- predictor: warp per node ----------------
__global__ void k_pred(const float* __restrict__ Wp1, const float* __restrict__ bp1,
                       const float* __restrict__ Wp3, const float* __restrict__ bp3,
                       float* __restrict__ out){
    int warp = threadIdx.x >> 5, lane = threadIdx.x & 31;
    int n = blockIdx.x*8 + warp;
    const float* row = g_gatout + (size_t)n*CD;
    float w1 = Wp1[lane];
    float b1 = bp1[0];
    float p[TT];
    #pragma unroll
    for (int t = 0; t < TT; t++){
        float s = row[t*HID + lane]*w1;
        #pragma unroll
        for (int o = 16; o; o >>= 1) s += __shfl_xor_sync(0xffffffffu, s, o);
        s += b1;
        p[t] = (s > 0.f) ? s : 0.f;
    }
    if (lane < PLEN){
        float q = bp3[lane];
        #pragma unroll
        for (int t = 0; t < TT; t++) q += p[t]*Wp3[lane*TT + t];
        out[(size_t)n*PLEN + lane] = (q > 0.f) ? q : 0.f;
    }
}

// ---------------- batch max-pool ----------------
__global__ void k_pool(const int* __restrict__ bv){
    int g0 = blockIdx.x*128;
    int c  = threadIdx.x;
    int b  = bv[g0];
    float m = -3.0e38f;
    for (int i = 0; i < 128; i++){
        float v = g_gatout[(size_t)(g0+i)*CD + c];
        m = fmaxf(m, v);
    }
    atomicMax(&g_pooled[b*CD + c], fenc(m));
}

// ---------------- classifier + softmax ----------------
__global__ void k_cls(const float* __restrict__ Wc1, const float* __restrict__ bc1,
                      const float* __restrict__ Wc2, const float* __restrict__ bc2,
                      float* __restrict__ out, int out_size){
    __shared__ float l1[NB][32];
    __shared__ float l2[NB][2];
    int tid = threadIdx.x;
    int b = tid >> 5, i = tid & 31;
    float a = bc1[i];
    for (int c = 0; c < CD; c++) a += fdec(g_pooled[b*CD + c]) * Wc1[i*CD + c];
    l1[b][i] = a;
    __syncthreads();
    if (tid < NB*2){
        int bb = tid >> 1, j = tid & 1;
        float v = bc2[j];
        for (int k = 0; k < 32; k++) v += l1[bb][k]*Wc2[j*32 + k];
        l2[bb][j] = v;
    }
    __syncthreads();
    if (tid < NB*2){
        int bb = tid >> 1, j = tid & 1;
        float m = fmaxf(l2[bb][0], l2[bb][1]);
        float e0 = __expf(l2[bb][0] - m), e1 = __expf(l2[bb][1] - m);
        out[out_size - NB*2 + bb*2 + j] = ((j == 0) ? e0 : e1) / (e0 + e1);
    }
}

// ---------------- launch: forked-stream DAG with agg/gemm pipelining ----------------
extern "C" void kernel_launch(void* const* d_in, const int* in_sizes, int n_in,
                              void* d_out, int out_size){
    const float* x   = (const float*)d_in[0];
    const int*   ei  = (const int*)  d_in[1];
    const float* ea  = (const float*)d_in[2];
    const int*   bv  = (const int*)  d_in[3];
    int wb = (n_in >= 23 && in_sizes[4] == 1) ? 5 : 4;
    const float* Wih      = (const float*)d_in[wb+0];
    const float* Whh      = (const float*)d_in[wb+1];
    const float* bih      = (const float*)d_in[wb+2];
    const float* bhh      = (const float*)d_in[wb+3];
    const float* Wgat     = (const float*)d_in[wb+4];
    const float* att_src  = (const float*)d_in[wb+5];
    const float* att_dst  = (const float*)d_in[wb+6];
    const float* Wedge    = (const float*)d_in[wb+7];
    const float* att_edge = (const float*)d_in[wb+8];
    const float* gat_bias = (const float*)d_in[wb+9];
    const float* Wp1      = (const float*)d_in[wb+10];
    const float* bp1      = (const float*)d_in[wb+11];
    const float* Wp3      = (const float*)d_in[wb+12];
    const float* bp3      = (const float*)d_in[wb+13];
    const float* Wc1      = (const float*)d_in[wb+14];
    const float* bc1      = (const float*)d_in[wb+15];
    const float* Wc2      = (const float*)d_in[wb+16];
    const float* bc2      = (const float*)d_in[wb+17];
    float* out = (float*)d_out;

    static cudaStream_t s2 = 0, s3 = 0;
    static cudaEvent_t evRoot = 0, evInit = 0, evVecs = 0, evScan = 0, evB16 = 0;
    static cudaEvent_t evAgg0 = 0, evGemm0 = 0, evGemmAll = 0, evCls = 0;
    if (!s2){
        cudaStreamCreateWithFlags(&s2, cudaStreamNonBlocking);
        cudaStreamCreateWithFlags(&s3, cudaStreamNonBlocking);
        cudaEventCreateWithFlags(&evRoot,    cudaEventDisableTiming);
        cudaEventCreateWithFlags(&evInit,    cudaEventDisableTiming);
        cudaEventCreateWithFlags(&evVecs,    cudaEventDisableTiming);
        cudaEventCreateWithFlags(&evScan,    cudaEventDisableTiming);
        cudaEventCreateWithFlags(&evB16,     cudaEventDisableTiming);
        cudaEventCreateWithFlags(&evAgg0,    cudaEventDisableTiming);
        cudaEventCreateWithFlags(&evGemm0,   cudaEventDisableTiming);
        cudaEventCreateWithFlags(&evGemmAll, cudaEventDisableTiming);
        cudaEventCreateWithFlags(&evCls,     cudaEventDisableTiming);
        cudaFuncSetAttribute(k_gemm_mma, cudaFuncAttributeMaxDynamicSharedMemorySize, GSM_TOT);
    }

    // root fork point (empty main stream, capture-legal)
    cudaEventRecord(evRoot, 0);

    // s3: vecs (no deps!) -> b16; later gemm lower half
    cudaStreamWaitEvent(s3, evRoot, 0);
    k_vecs_r<<<dim3(12, 3), 256, 0, s3>>>(Wgat, att_src, att_dst);
    cudaEventRecord(evVecs, s3);
    k_b16   <<<(CD*KDIM + 255)/256, 256, 0, s3>>>(Wgat);
    cudaEventRecord(evB16, s3);

    // main: init
    k_init <<<96, 256>>>(Wedge, att_edge);
    cudaEventRecord(evInit, 0);

    // s2: count + scan (needs init for zeroed g_count)
    cudaStreamWaitEvent(s2, evInit, 0);
    k_count<<<NE/1024, 256, 0, s2>>>(ei);
    k_scan <<<1, 1024, 0, s2>>>();
    cudaEventRecord(evScan, s2);

    // main: gru2 (needs vecs), then edge pipeline
    cudaStreamWaitEvent(0, evVecs, 0);
    k_gru2 <<<512, 128>>>(x, Wih, Whh, bih, bhh);
    cudaStreamWaitEvent(0, evScan, 0);
    k_scw  <<<NE/256, 256>>>(ei, ea);
    k_agg  <<<NNODES/2, 128>>>(0);
    cudaEventRecord(evAgg0, 0);
    k_agg  <<<NNODES/2, 128>>>(NNODES/2);

    // s3: gemm lower half overlapped with agg upper half
    cudaStreamWaitEvent(s3, evAgg0, 0);
    k_gemm_mma<<<dim3(2, 32), 384, GSM_TOT, s3>>>(gat_bias, 0);
    cudaEventRecord(evGemm0, s3);

    // main: gemm upper half (needs b16)
    cudaStreamWaitEvent(0, evB16, 0);
    k_gemm_mma<<<dim3(2, 32), 384, GSM_TOT>>>(gat_bias, 32);
    cudaStreamWaitEvent(0, evGemm0, 0);
    cudaEventRecord(evGemmAll, 0);

    // s2: pool + cls after full gemm
    cudaStreamWaitEvent(s2, evGemmAll, 0);
    k_pool <<<64, 384, 0, s2>>>(bv);
    k_cls  <<<1, 256, 0, s2>>>(Wc1, bc1, Wc2, bc2, out, out_size);
    cudaEventRecord(evCls, s2);

    // main: pred, then join cls
    k_pred <<<1024, 256>>>(Wp1, bp1, Wp3, bp3, out);
    cudaStreamWaitEvent(0, evCls, 0);
}